// round 1
// baseline (speedup 1.0000x reference)
#include <cuda_runtime.h>

#define BB 4
#define TT 4096
#define CC 512
#define HH 64

// scratch for projected q, k, v  (static device globals — allocation-free)
__device__ float g_q[BB * TT * HH];
__device__ float g_k[BB * TT * HH];
__device__ float g_v[BB * TT * HH];

// ---------------------------------------------------------------------------
// Projection: [M=16384, K=512] x [512, 192] -> k|q|v, tiled SMEM GEMM
// CTA: 256 threads, tile 64 rows x 192 cols, micro 4x12
// ---------------------------------------------------------------------------
__global__ __launch_bounds__(256) void proj_kernel(
    const float* __restrict__ x,
    const float* __restrict__ Wk,
    const float* __restrict__ Wq,
    const float* __restrict__ Wv)
{
    extern __shared__ float sm[];
    float* xs = sm;                 // [64 cc][65 r]  (stride 65)
    float* ws = sm + 64 * 65;       // [64 cc][196 n] (stride 196)

    const int tid = threadIdx.x;
    const int tx = tid & 15;
    const int ty = tid >> 4;
    const int row0 = blockIdx.x * 64;

    float acc[4][12];
#pragma unroll
    for (int i = 0; i < 4; i++)
#pragma unroll
        for (int j = 0; j < 12; j++) acc[i][j] = 0.f;

    for (int c0 = 0; c0 < CC; c0 += 64) {
        __syncthreads();
        // x tile: coalesced over cc, conflict-free smem store (stride 65)
        for (int idx = tid; idx < 64 * 64; idx += 256) {
            int r = idx >> 6, cc = idx & 63;
            xs[cc * 65 + r] = x[(size_t)(row0 + r) * CC + c0 + cc];
        }
        // w tile: 64 x 192 (Wk | Wq | Wv)
        for (int idx = tid; idx < 64 * 192; idx += 256) {
            int cc = idx / 192, n = idx - cc * 192;
            const float* W = (n < 64) ? Wk : (n < 128) ? Wq : Wv;
            ws[cc * 196 + n] = W[(size_t)(c0 + cc) * HH + (n & 63)];
        }
        __syncthreads();

#pragma unroll 4
        for (int cc = 0; cc < 64; cc++) {
            float xv[4], wv[12];
#pragma unroll
            for (int i = 0; i < 4; i++) xv[i] = xs[cc * 65 + 4 * ty + i];
#pragma unroll
            for (int j = 0; j < 12; j++) wv[j] = ws[cc * 196 + tx + 16 * j];
#pragma unroll
            for (int i = 0; i < 4; i++)
#pragma unroll
                for (int j = 0; j < 12; j++)
                    acc[i][j] += xv[i] * wv[j];
        }
    }

#pragma unroll
    for (int i = 0; i < 4; i++) {
        int row = row0 + 4 * ty + i;
#pragma unroll
        for (int j = 0; j < 12; j++) {
            int n = tx + 16 * j;
            float* dst = (n < 64) ? g_k : (n < 128) ? g_q : g_v;
            dst[(size_t)row * HH + (n & 63)] = acc[i][j];
        }
    }
}

// ---------------------------------------------------------------------------
// Flash attention (causal, scale = C^-0.5), fp32.
// CTA: 256 threads (16x16), Q tile 64 x H, K/V tiles 64 x H, micro 4x4.
// SMEM stride 68 floats keeps float4 16B alignment; 4 * 64*68*4 = 69632 B.
// ---------------------------------------------------------------------------
__global__ __launch_bounds__(256) void attn_kernel(float* __restrict__ out)
{
    extern __shared__ float sm[];
    float* Qs = sm;                 // [h][r]   stride 68
    float* Ks = sm + 64 * 68;       // [h][c]
    float* Vs = sm + 2 * 64 * 68;   // [k][c]
    float* Ss = sm + 3 * 64 * 68;   // [r][k]  (P tile)

    const int tid = threadIdx.x;
    const int tx = tid & 15;
    const int ty = tid >> 4;
    // heavy (late) query tiles first to reduce tail imbalance
    const int qt = (int)gridDim.x - 1 - (int)blockIdx.x;
    const int b = blockIdx.y;
    const size_t base = (size_t)b * TT * HH;
    const int q0 = qt * 64;

    // load Q tile transposed: Qs[h][r]
    for (int idx = tid; idx < 64 * 64; idx += 256) {
        int r = idx >> 6, h = idx & 63;
        Qs[h * 68 + r] = g_q[base + (size_t)(q0 + r) * HH + h];
    }

    float mrow[4], lrow[4], acc[4][4];
#pragma unroll
    for (int i = 0; i < 4; i++) {
        mrow[i] = -1e30f;
        lrow[i] = 0.f;
#pragma unroll
        for (int j = 0; j < 4; j++) acc[i][j] = 0.f;
    }

    const float scale = 0.044194173824159216f;  // 512^-0.5

    for (int kt = 0; kt <= qt; kt++) {
        const int k0 = kt * 64;
        __syncthreads();  // previous iteration's Ss/Vs reads done; also covers Q load (kt==0)
        for (int idx = tid; idx < 64 * 64; idx += 256) {
            int c = idx >> 6, h = idx & 63;
            Ks[h * 68 + c] = g_k[base + (size_t)(k0 + c) * HH + h];
        }
        for (int idx = tid; idx < 64 * 64; idx += 256) {
            int k = idx >> 6, c = idx & 63;
            Vs[k * 68 + c] = g_v[base + (size_t)(k0 + k) * HH + c];
        }
        __syncthreads();

        // S = Q K^T for this tile; micro 4x4
        float s[4][4];
#pragma unroll
        for (int i = 0; i < 4; i++)
#pragma unroll
            for (int j = 0; j < 4; j++) s[i][j] = 0.f;

#pragma unroll 8
        for (int h = 0; h < 64; h++) {
            float4 qv = *(const float4*)&Qs[h * 68 + 4 * ty];
            float4 kv = *(const float4*)&Ks[h * 68 + 4 * tx];
            float qa[4] = {qv.x, qv.y, qv.z, qv.w};
            float ka[4] = {kv.x, kv.y, kv.z, kv.w};
#pragma unroll
            for (int i = 0; i < 4; i++)
#pragma unroll
                for (int j = 0; j < 4; j++)
                    s[i][j] += qa[i] * ka[j];
        }

        const bool diag = (kt == qt);
#pragma unroll
        for (int i = 0; i < 4; i++) {
            int qi = q0 + 4 * ty + i;
#pragma unroll
            for (int j = 0; j < 4; j++) {
                s[i][j] *= scale;
                if (diag && (k0 + 4 * tx + j > qi)) s[i][j] = -1e30f;
            }
        }

        // online softmax; rows are split across the 16 tx lanes
#pragma unroll
        for (int i = 0; i < 4; i++) {
            float mx = fmaxf(fmaxf(s[i][0], s[i][1]), fmaxf(s[i][2], s[i][3]));
#pragma unroll
            for (int d = 1; d < 16; d <<= 1)
                mx = fmaxf(mx, __shfl_xor_sync(0xffffffffu, mx, d));
            float mn = fmaxf(mrow[i], mx);
            float alpha = __expf(mrow[i] - mn);
            float rs = 0.f;
#pragma unroll
            for (int j = 0; j < 4; j++) {
                s[i][j] = __expf(s[i][j] - mn);   // now P
                rs += s[i][j];
            }
#pragma unroll
            for (int d = 1; d < 16; d <<= 1)
                rs += __shfl_xor_sync(0xffffffffu, rs, d);
            lrow[i] = lrow[i] * alpha + rs;
            mrow[i] = mn;
#pragma unroll
            for (int j = 0; j < 4; j++) acc[i][j] *= alpha;
            // publish P row chunk (16B-aligned float4 store)
            float4 pv = make_float4(s[i][0], s[i][1], s[i][2], s[i][3]);
            *(float4*)&Ss[(4 * ty + i) * 68 + 4 * tx] = pv;
        }
        __syncthreads();

        // O += P V
#pragma unroll 8
        for (int k = 0; k < 64; k++) {
            float4 vv = *(const float4*)&Vs[k * 68 + 4 * tx];
#pragma unroll
            for (int i = 0; i < 4; i++) {
                float p = Ss[(4 * ty + i) * 68 + k];
                acc[i][0] += p * vv.x;
                acc[i][1] += p * vv.y;
                acc[i][2] += p * vv.z;
                acc[i][3] += p * vv.w;
            }
        }
    }

    // epilogue: normalize and store
#pragma unroll
    for (int i = 0; i < 4; i++) {
        float inv = 1.0f / lrow[i];
        int row = q0 + 4 * ty + i;
#pragma unroll
        for (int j = 0; j < 4; j++)
            out[base + (size_t)row * HH + 4 * tx + j] = acc[i][j] * inv;
    }
}

// ---------------------------------------------------------------------------
extern "C" void kernel_launch(void* const* d_in, const int* in_sizes, int n_in,
                              void* d_out, int out_size)
{
    const float* x  = (const float*)d_in[0];
    const float* Wk = (const float*)d_in[1];
    const float* Wq = (const float*)d_in[2];
    const float* Wv = (const float*)d_in[3];
    float* out = (float*)d_out;

    const int smem_proj = (64 * 65 + 64 * 196) * (int)sizeof(float);   // ~66.8 KB
    const int smem_attn = 4 * 64 * 68 * (int)sizeof(float);            // ~69.6 KB

    cudaFuncSetAttribute(proj_kernel, cudaFuncAttributeMaxDynamicSharedMemorySize, smem_proj);
    cudaFuncSetAttribute(attn_kernel, cudaFuncAttributeMaxDynamicSharedMemorySize, smem_attn);

    proj_kernel<<<(BB * TT) / 64, 256, smem_proj>>>(x, Wk, Wq, Wv);
    attn_kernel<<<dim3(TT / 64, BB), 256, smem_attn>>>(out);
}

// round 3
// speedup vs baseline: 3.9480x; 3.9480x over previous
#include <cuda_runtime.h>
#include <cstdint>

#define BB 4
#define TT 4096
#define CC 512
#define HH 64
#define SDIM 68
#define SCALE 0.044194173824159216f   // 512^-0.5

// projected q (pre-scaled), k, v — tf32-rounded fp32
__device__ float g_q[BB * TT * HH];
__device__ float g_k[BB * TT * HH];
__device__ float g_v[BB * TT * HH];
// split-K partials: 4 b x 64 qtiles x 8 chunks = 2048 units
__device__ float g_opart[2048 * 64 * 64];
__device__ float g_mpart[2048 * 64];
__device__ float g_lpart[2048 * 64];

__device__ __forceinline__ float tf32r(float x) {
    uint32_t t;
    asm("cvt.rna.tf32.f32 %0, %1;" : "=r"(t) : "f"(x));
    return __uint_as_float(t);
}

__device__ __forceinline__ void mma_tf32(float* d, const uint32_t* a,
                                         uint32_t b0, uint32_t b1) {
    asm volatile(
        "mma.sync.aligned.m16n8k8.row.col.f32.tf32.tf32.f32 "
        "{%0,%1,%2,%3}, {%4,%5,%6,%7}, {%8,%9}, {%0,%1,%2,%3};"
        : "+f"(d[0]), "+f"(d[1]), "+f"(d[2]), "+f"(d[3])
        : "r"(a[0]), "r"(a[1]), "r"(a[2]), "r"(a[3]), "r"(b0), "r"(b1));
}

// ---------------------------------------------------------------------------
// Projection: [16384, 512] x [512, 192] -> k|q|v (q pre-scaled, all tf32-rounded)
// ---------------------------------------------------------------------------
__global__ __launch_bounds__(256) void proj_kernel(
    const float* __restrict__ x,
    const float* __restrict__ Wk,
    const float* __restrict__ Wq,
    const float* __restrict__ Wv)
{
    extern __shared__ float sm[];
    float* xs = sm;                 // [64 cc][65 r]
    float* ws = sm + 64 * 65;       // [64 cc][196 n]

    const int tid = threadIdx.x;
    const int tx = tid & 15;
    const int ty = tid >> 4;
    const int row0 = blockIdx.x * 64;

    float acc[4][12];
#pragma unroll
    for (int i = 0; i < 4; i++)
#pragma unroll
        for (int j = 0; j < 12; j++) acc[i][j] = 0.f;

    for (int c0 = 0; c0 < CC; c0 += 64) {
        __syncthreads();
        for (int idx = tid; idx < 64 * 64; idx += 256) {
            int r = idx >> 6, cc = idx & 63;
            xs[cc * 65 + r] = x[(size_t)(row0 + r) * CC + c0 + cc];
        }
        for (int idx = tid; idx < 64 * 192; idx += 256) {
            int cc = idx / 192, n = idx - cc * 192;
            const float* W = (n < 64) ? Wk : (n < 128) ? Wq : Wv;
            ws[cc * 196 + n] = W[(size_t)(c0 + cc) * HH + (n & 63)];
        }
        __syncthreads();

#pragma unroll 4
        for (int cc = 0; cc < 64; cc++) {
            float xv[4], wv[12];
#pragma unroll
            for (int i = 0; i < 4; i++) xv[i] = xs[cc * 65 + 4 * ty + i];
#pragma unroll
            for (int j = 0; j < 12; j++) wv[j] = ws[cc * 196 + tx + 16 * j];
#pragma unroll
            for (int i = 0; i < 4; i++)
#pragma unroll
                for (int j = 0; j < 12; j++)
                    acc[i][j] += xv[i] * wv[j];
        }
    }

#pragma unroll
    for (int i = 0; i < 4; i++) {
        int row = row0 + 4 * ty + i;
#pragma unroll
        for (int j = 0; j < 12; j++) {
            int n = tx + 16 * j;
            float* dst = (n < 64) ? g_k : (n < 128) ? g_q : g_v;
            float v = (n >= 64 && n < 128) ? acc[i][j] * SCALE : acc[i][j];
            dst[(size_t)row * HH + (n & 63)] = tf32r(v);
        }
    }
}

// ---------------------------------------------------------------------------
// Split-K flash attention partial. CTA = 128 thr (4 warps), warp w owns rows
// 16w..16w+15 of a 64-row q tile. Chunk = up to 8 k-tiles of 64 keys.
// Both GEMMs on HMMA tf32 m16n8k8. Unnormalized O + (m, l) per row to scratch.
// ---------------------------------------------------------------------------
__global__ __launch_bounds__(128) void attn_partial()
{
    const int ch = blockIdx.x, qt = blockIdx.y, b = blockIdx.z;
    if (ch * 8 > qt) return;    // chunk entirely above causal boundary

    extern __shared__ float sm[];
    float* Qs = sm;                       // reused as Ps after frag preload
    float* Ks = sm + 64 * SDIM;           // [key][h]
    float* Vt = sm + 2 * 64 * SDIM;       // [h][key]
    uint32_t* Qs_u = (uint32_t*)Qs;
    uint32_t* Ks_u = (uint32_t*)Ks;
    uint32_t* Vt_u = (uint32_t*)Vt;
    float* Ps = Qs;
    uint32_t* Ps_u = Qs_u;

    const int tid = threadIdx.x;
    const int w = tid >> 5;
    const int lane = tid & 31;
    const int r = lane >> 2;              // 0..7
    const int c = lane & 3;               // 0..3
    const int rowA = 16 * w + r;          // local S row (regs 0,1); +8 for regs 2,3
    const int q0 = qt * 64;
    const size_t base = (size_t)b * TT * HH;
    const int unit = (b * 64 + qt) * 8 + ch;

    // Q tile -> smem (values already tf32 + scaled)
    for (int i = tid; i < 64 * 16; i += 128) {
        int row = i >> 4, c4 = (i & 15) * 4;
        *(float4*)&Qs[row * SDIM + c4] =
            *(const float4*)&g_q[base + (size_t)(q0 + row) * HH + c4];
    }
    __syncthreads();

    // preload Q A-fragments for all 8 k-steps (stay in regs whole kernel)
    uint32_t qf[8][4];
#pragma unroll
    for (int kk = 0; kk < 8; kk++) {
        qf[kk][0] = Qs_u[rowA * SDIM + kk * 8 + c];
        qf[kk][1] = Qs_u[(rowA + 8) * SDIM + kk * 8 + c];
        qf[kk][2] = Qs_u[rowA * SDIM + kk * 8 + c + 4];
        qf[kk][3] = Qs_u[(rowA + 8) * SDIM + kk * 8 + c + 4];
    }

    float mA = -1e30f, mB = -1e30f, lA = 0.f, lB = 0.f;
    float o[8][4];
#pragma unroll
    for (int nf = 0; nf < 8; nf++)
#pragma unroll
        for (int j = 0; j < 4; j++) o[nf][j] = 0.f;

    const int kt_end = min(ch * 8 + 8, qt + 1);
    for (int kt = ch * 8; kt < kt_end; kt++) {
        const int k0 = kt * 64;
        __syncthreads();    // prior-iter frag reads of Ks/Vt/Ps complete
        for (int i = tid; i < 64 * 16; i += 128) {
            int key = i >> 4, c4 = (i & 15) * 4;
            *(float4*)&Ks[key * SDIM + c4] =
                *(const float4*)&g_k[base + (size_t)(k0 + key) * HH + c4];
        }
        for (int i = tid; i < 64 * 16; i += 128) {
            int key = i & 63, h4 = (i >> 6) * 4;
            float4 vv = *(const float4*)&g_v[base + (size_t)(k0 + key) * HH + h4];
            Vt[(h4 + 0) * SDIM + key] = vv.x;
            Vt[(h4 + 1) * SDIM + key] = vv.y;
            Vt[(h4 + 2) * SDIM + key] = vv.z;
            Vt[(h4 + 3) * SDIM + key] = vv.w;
        }
        __syncthreads();

        // S = Q K^T : 8 n-frags x 8 k-steps
        float s[8][4];
#pragma unroll
        for (int nf = 0; nf < 8; nf++) {
#pragma unroll
            for (int j = 0; j < 4; j++) s[nf][j] = 0.f;
#pragma unroll
            for (int kk = 0; kk < 8; kk++) {
                uint32_t b0 = Ks_u[(nf * 8 + r) * SDIM + kk * 8 + c];
                uint32_t b1 = Ks_u[(nf * 8 + r) * SDIM + kk * 8 + c + 4];
                mma_tf32(s[nf], qf[kk], b0, b1);
            }
        }

        // causal mask (only diagonal tile); scale already folded into q
        if (kt == qt) {
            int gA = q0 + rowA;
#pragma unroll
            for (int nf = 0; nf < 8; nf++) {
                int col = k0 + nf * 8 + 2 * c;
                if (col > gA)     s[nf][0] = -1e30f;
                if (col + 1 > gA) s[nf][1] = -1e30f;
                if (col > gA + 8)     s[nf][2] = -1e30f;
                if (col + 1 > gA + 8) s[nf][3] = -1e30f;
            }
        }

        // online softmax (rows rowA, rowA+8); quad = lanes sharing a row
        float xA = -1e30f, xB = -1e30f;
#pragma unroll
        for (int nf = 0; nf < 8; nf++) {
            xA = fmaxf(xA, fmaxf(s[nf][0], s[nf][1]));
            xB = fmaxf(xB, fmaxf(s[nf][2], s[nf][3]));
        }
#pragma unroll
        for (int d = 1; d < 4; d <<= 1) {
            xA = fmaxf(xA, __shfl_xor_sync(0xffffffffu, xA, d));
            xB = fmaxf(xB, __shfl_xor_sync(0xffffffffu, xB, d));
        }
        float mnA = fmaxf(mA, xA), mnB = fmaxf(mB, xB);
        float aA = __expf(mA - mnA), aB = __expf(mB - mnB);

        float sumA = 0.f, sumB = 0.f;
#pragma unroll
        for (int nf = 0; nf < 8; nf++) {
            float p0 = __expf(s[nf][0] - mnA);
            float p1 = __expf(s[nf][1] - mnA);
            float p2 = __expf(s[nf][2] - mnB);
            float p3 = __expf(s[nf][3] - mnB);
            sumA += p0 + p1;
            sumB += p2 + p3;
            int colo = nf * 8 + 2 * c;
            *(float2*)&Ps[rowA * SDIM + colo] =
                make_float2(tf32r(p0), tf32r(p1));
            *(float2*)&Ps[(rowA + 8) * SDIM + colo] =
                make_float2(tf32r(p2), tf32r(p3));
        }
#pragma unroll
        for (int d = 1; d < 4; d <<= 1) {
            sumA += __shfl_xor_sync(0xffffffffu, sumA, d);
            sumB += __shfl_xor_sync(0xffffffffu, sumB, d);
        }
        lA = lA * aA + sumA;
        lB = lB * aB + sumB;
        mA = mnA;
        mB = mnB;
#pragma unroll
        for (int nf = 0; nf < 8; nf++) {
            o[nf][0] *= aA; o[nf][1] *= aA;
            o[nf][2] *= aB; o[nf][3] *= aB;
        }
        __syncthreads();    // Ps visible to whole CTA

        // O += P V : A-frag from Ps, B-frag from Vt
#pragma unroll
        for (int kk = 0; kk < 8; kk++) {
            uint32_t a[4];
            a[0] = Ps_u[rowA * SDIM + kk * 8 + c];
            a[1] = Ps_u[(rowA + 8) * SDIM + kk * 8 + c];
            a[2] = Ps_u[rowA * SDIM + kk * 8 + c + 4];
            a[3] = Ps_u[(rowA + 8) * SDIM + kk * 8 + c + 4];
#pragma unroll
            for (int nf = 0; nf < 8; nf++) {
                uint32_t b0 = Vt_u[(nf * 8 + r) * SDIM + kk * 8 + c];
                uint32_t b1 = Vt_u[(nf * 8 + r) * SDIM + kk * 8 + c + 4];
                mma_tf32(o[nf], a, b0, b1);
            }
        }
    }

    // write partial O (unnormalized) + per-row m, l
#pragma unroll
    for (int nf = 0; nf < 8; nf++) {
        int colo = nf * 8 + 2 * c;
        *(float2*)&g_opart[(size_t)unit * 4096 + rowA * 64 + colo] =
            make_float2(o[nf][0], o[nf][1]);
        *(float2*)&g_opart[(size_t)unit * 4096 + (rowA + 8) * 64 + colo] =
            make_float2(o[nf][2], o[nf][3]);
    }
    if (c == 0) {
        g_mpart[unit * 64 + rowA] = mA;
        g_mpart[unit * 64 + rowA + 8] = mB;
        g_lpart[unit * 64 + rowA] = lA;
        g_lpart[unit * 64 + rowA + 8] = lB;
    }
}

// ---------------------------------------------------------------------------
// Combine: log-sum-exp merge of up to 8 chunk partials per (b, qtile).
// ---------------------------------------------------------------------------
__global__ __launch_bounds__(128) void attn_combine(float* __restrict__ out)
{
    const int qt = blockIdx.x, b = blockIdx.y;
    const int tid = threadIdx.x;
    const int row = tid >> 1;
    const int half = tid & 1;
    const int nch = (qt >> 3) + 1;
    const int ubase = (b * 64 + qt) * 8;

    float M = -1e30f;
    for (int i = 0; i < nch; i++)
        M = fmaxf(M, g_mpart[(ubase + i) * 64 + row]);

    float L = 0.f;
    float acc[32];
#pragma unroll
    for (int j = 0; j < 32; j++) acc[j] = 0.f;

    for (int i = 0; i < nch; i++) {
        float coef = __expf(g_mpart[(ubase + i) * 64 + row] - M);
        L += coef * g_lpart[(ubase + i) * 64 + row];
        const float* src =
            &g_opart[(size_t)(ubase + i) * 4096 + row * 64 + half * 32];
#pragma unroll
        for (int j = 0; j < 8; j++) {
            float4 v = *(const float4*)&src[4 * j];
            acc[4 * j + 0] += coef * v.x;
            acc[4 * j + 1] += coef * v.y;
            acc[4 * j + 2] += coef * v.z;
            acc[4 * j + 3] += coef * v.w;
        }
    }

    float inv = 1.f / L;
    float* dst = &out[(size_t)b * TT * HH + (size_t)(qt * 64 + row) * HH + half * 32];
#pragma unroll
    for (int j = 0; j < 8; j++) {
        float4 v = make_float4(acc[4 * j] * inv, acc[4 * j + 1] * inv,
                               acc[4 * j + 2] * inv, acc[4 * j + 3] * inv);
        *(float4*)&dst[4 * j] = v;
    }
}

// ---------------------------------------------------------------------------
extern "C" void kernel_launch(void* const* d_in, const int* in_sizes, int n_in,
                              void* d_out, int out_size)
{
    const float* x  = (const float*)d_in[0];
    const float* Wk = (const float*)d_in[1];
    const float* Wq = (const float*)d_in[2];
    const float* Wv = (const float*)d_in[3];
    float* out = (float*)d_out;

    const int smem_proj = (64 * 65 + 64 * 196) * (int)sizeof(float);
    const int smem_attn = 3 * 64 * SDIM * (int)sizeof(float);   // 52.2 KB

    cudaFuncSetAttribute(proj_kernel, cudaFuncAttributeMaxDynamicSharedMemorySize, smem_proj);
    cudaFuncSetAttribute(attn_partial, cudaFuncAttributeMaxDynamicSharedMemorySize, smem_attn);

    proj_kernel<<<(BB * TT) / 64, 256, smem_proj>>>(x, Wk, Wq, Wv);
    attn_partial<<<dim3(8, 64, BB), 128, smem_attn>>>();
    attn_combine<<<dim3(64, BB), 128>>>(out);
}

// round 4
// speedup vs baseline: 5.1979x; 1.3166x over previous
#include <cuda_runtime.h>
#include <cstdint>

#define BB 4
#define TT 4096
#define CC 512
#define HH 64
#define SDIM 68
#define SCALE 0.044194173824159216f   // 512^-0.5

// projected q (pre-scaled), k, v — tf32-rounded fp32
__device__ float g_q[BB * TT * HH];
__device__ float g_k[BB * TT * HH];
__device__ float g_v[BB * TT * HH];
// W transposed + hi/lo tf32 split: [192 n][512 k]
__device__ float g_wthi[192 * 512];
__device__ float g_wtlo[192 * 512];
// split-K partials
__device__ float g_opart[2048 * 64 * 64];
__device__ float g_mpart[2048 * 64];
__device__ float g_lpart[2048 * 64];

__device__ __forceinline__ float tf32r(float x) {
    uint32_t t;
    asm("cvt.rna.tf32.f32 %0, %1;" : "=r"(t) : "f"(x));
    return __uint_as_float(t);
}
__device__ __forceinline__ uint32_t tf32u(float x) {
    uint32_t t;
    asm("cvt.rna.tf32.f32 %0, %1;" : "=r"(t) : "f"(x));
    return t;
}

__device__ __forceinline__ void mma_tf32(float* d, const uint32_t* a,
                                         uint32_t b0, uint32_t b1) {
    asm volatile(
        "mma.sync.aligned.m16n8k8.row.col.f32.tf32.tf32.f32 "
        "{%0,%1,%2,%3}, {%4,%5,%6,%7}, {%8,%9}, {%0,%1,%2,%3};"
        : "+f"(d[0]), "+f"(d[1]), "+f"(d[2]), "+f"(d[3])
        : "r"(a[0]), "r"(a[1]), "r"(a[2]), "r"(a[3]), "r"(b0), "r"(b1));
}

__device__ __forceinline__ void cp16(uint32_t dst, const void* src) {
    asm volatile("cp.async.cg.shared.global [%0], [%1], 16;"
                 :: "r"(dst), "l"(src) : "memory");
}
#define CP_COMMIT() asm volatile("cp.async.commit_group;" ::: "memory")
#define CP_WAIT1() asm volatile("cp.async.wait_group 1;" ::: "memory")
#define CP_WAIT0() asm volatile("cp.async.wait_group 0;" ::: "memory")

// ---------------------------------------------------------------------------
// W transpose + tf32 hi/lo split: g_wt{hi,lo}[n][k] = split(W(k, n))
// ---------------------------------------------------------------------------
__global__ __launch_bounds__(256) void wt_kernel(
    const float* __restrict__ Wk,
    const float* __restrict__ Wq,
    const float* __restrict__ Wv)
{
    int idx = blockIdx.x * 256 + threadIdx.x;   // 384 blocks x 256 = 98304
    int k = idx / 192, n = idx - k * 192;
    const float* W = (n < 64) ? Wk : (n < 128) ? Wq : Wv;
    float w = W[k * HH + (n & 63)];
    float hi = tf32r(w);
    g_wthi[n * CC + k] = hi;
    g_wtlo[n * CC + k] = tf32r(w - hi);
}

// ---------------------------------------------------------------------------
// Projection on HMMA tf32 (3-term emulated fp32).
// CTA 256 thr (8 warps): tile M=128 x N=192, K-chunk 32, cp.async dbl-buffer.
// Warp (mw = w>>2, nw = w&3): rows 64*mw+16*mf, cols 48*nw+8*nf. 4 mf x 6 nf.
// ---------------------------------------------------------------------------
#define PB_X 0
#define PB_WH 4608
#define PB_WL 11520
#define PB_STRIDE 18432   // floats per buffer
#define PSMEM (2 * PB_STRIDE * 4)

__global__ __launch_bounds__(256, 1) void proj_mma(const float* __restrict__ x)
{
    extern __shared__ float sm[];
    uint32_t sbase;
    asm("{ .reg .u64 t; cvta.to.shared.u64 t, %1; cvt.u32.u64 %0, t; }"
        : "=r"(sbase) : "l"(sm));

    const int tid = threadIdx.x;
    const int w = tid >> 5;
    const int lane = tid & 31;
    const int gr = lane >> 2;
    const int gc = lane & 3;
    const int mw = w >> 2, nw = w & 3;
    const int row0 = blockIdx.x * 128;

    float acc[4][6][4];
#pragma unroll
    for (int mf = 0; mf < 4; mf++)
#pragma unroll
        for (int nf = 0; nf < 6; nf++)
#pragma unroll
            for (int j = 0; j < 4; j++) acc[mf][nf][j] = 0.f;

    // async-load one K-chunk into buffer `bo` (float offset)
    auto issue = [&](int ck, int bo) {
        const int k0 = ck * 32;
        for (int t = tid; t < 1024; t += 256) {      // X: 128 rows x 8 segs
            int r = t >> 3, s = t & 7;
            cp16(sbase + (bo + PB_X + r * 36 + s * 4) * 4,
                 &x[(size_t)(row0 + r) * CC + k0 + s * 4]);
        }
        for (int t = tid; t < 1536; t += 256) {      // W hi/lo: 192 rows x 8 segs
            int n = t >> 3, s = t & 7;
            cp16(sbase + (bo + PB_WH + n * 36 + s * 4) * 4,
                 &g_wthi[n * CC + k0 + s * 4]);
            cp16(sbase + (bo + PB_WL + n * 36 + s * 4) * 4,
                 &g_wtlo[n * CC + k0 + s * 4]);
        }
    };

    issue(0, 0);
    CP_COMMIT();

    for (int ck = 0; ck < 16; ck++) {
        const int bo = (ck & 1) * PB_STRIDE;
        if (ck + 1 < 16) {
            issue(ck + 1, ((ck + 1) & 1) * PB_STRIDE);
            CP_COMMIT();
            CP_WAIT1();
        } else {
            CP_WAIT0();
        }
        __syncthreads();

        const float* Xs = sm + bo + PB_X;
        const float* Wh = sm + bo + PB_WH;
        const float* Wl = sm + bo + PB_WL;

#pragma unroll
        for (int kk = 0; kk < 4; kk++) {
            uint32_t ah[4][4], al[4][4];
#pragma unroll
            for (int mf = 0; mf < 4; mf++) {
                int rb = 64 * mw + 16 * mf;
                float x0 = Xs[(rb + gr) * 36 + kk * 8 + gc];
                float x1 = Xs[(rb + gr + 8) * 36 + kk * 8 + gc];
                float x2 = Xs[(rb + gr) * 36 + kk * 8 + gc + 4];
                float x3 = Xs[(rb + gr + 8) * 36 + kk * 8 + gc + 4];
                ah[mf][0] = tf32u(x0);
                ah[mf][1] = tf32u(x1);
                ah[mf][2] = tf32u(x2);
                ah[mf][3] = tf32u(x3);
                al[mf][0] = tf32u(x0 - __uint_as_float(ah[mf][0]));
                al[mf][1] = tf32u(x1 - __uint_as_float(ah[mf][1]));
                al[mf][2] = tf32u(x2 - __uint_as_float(ah[mf][2]));
                al[mf][3] = tf32u(x3 - __uint_as_float(ah[mf][3]));
            }
#pragma unroll
            for (int nf = 0; nf < 6; nf++) {
                int nb = (48 * nw + 8 * nf + gr) * 36 + kk * 8 + gc;
                uint32_t bh0 = __float_as_uint(Wh[nb]);
                uint32_t bh1 = __float_as_uint(Wh[nb + 4]);
                uint32_t bl0 = __float_as_uint(Wl[nb]);
                uint32_t bl1 = __float_as_uint(Wl[nb + 4]);
#pragma unroll
                for (int mf = 0; mf < 4; mf++) {
                    mma_tf32(acc[mf][nf], ah[mf], bh0, bh1);
                    mma_tf32(acc[mf][nf], ah[mf], bl0, bl1);
                    mma_tf32(acc[mf][nf], al[mf], bh0, bh1);
                }
            }
        }
        __syncthreads();
    }

    // epilogue: scale q, round to tf32, scatter to g_k / g_q / g_v
#pragma unroll
    for (int mf = 0; mf < 4; mf++) {
#pragma unroll
        for (int nf = 0; nf < 6; nf++) {
            int n = 48 * nw + 8 * nf + 2 * gc;
            float* dst = (n < 64) ? g_k : (n < 128) ? g_q : g_v;
            float f = (n >= 64 && n < 128) ? SCALE : 1.0f;
            int r0 = row0 + 64 * mw + 16 * mf + gr;
            *(float2*)&dst[(size_t)r0 * HH + (n & 63)] =
                make_float2(tf32r(acc[mf][nf][0] * f), tf32r(acc[mf][nf][1] * f));
            *(float2*)&dst[(size_t)(r0 + 8) * HH + (n & 63)] =
                make_float2(tf32r(acc[mf][nf][2] * f), tf32r(acc[mf][nf][3] * f));
        }
    }
}

// ---------------------------------------------------------------------------
// Split-K flash attention partial (unchanged from R3).
// ---------------------------------------------------------------------------
__global__ __launch_bounds__(128) void attn_partial()
{
    const int ch = blockIdx.x, qt = blockIdx.y, b = blockIdx.z;
    if (ch * 8 > qt) return;

    extern __shared__ float sm[];
    float* Qs = sm;
    float* Ks = sm + 64 * SDIM;
    float* Vt = sm + 2 * 64 * SDIM;
    uint32_t* Qs_u = (uint32_t*)Qs;
    uint32_t* Ks_u = (uint32_t*)Ks;
    uint32_t* Vt_u = (uint32_t*)Vt;
    float* Ps = Qs;
    uint32_t* Ps_u = Qs_u;

    const int tid = threadIdx.x;
    const int w = tid >> 5;
    const int lane = tid & 31;
    const int r = lane >> 2;
    const int c = lane & 3;
    const int rowA = 16 * w + r;
    const int q0 = qt * 64;
    const size_t base = (size_t)b * TT * HH;
    const int unit = (b * 64 + qt) * 8 + ch;

    for (int i = tid; i < 64 * 16; i += 128) {
        int row = i >> 4, c4 = (i & 15) * 4;
        *(float4*)&Qs[row * SDIM + c4] =
            *(const float4*)&g_q[base + (size_t)(q0 + row) * HH + c4];
    }
    __syncthreads();

    uint32_t qf[8][4];
#pragma unroll
    for (int kk = 0; kk < 8; kk++) {
        qf[kk][0] = Qs_u[rowA * SDIM + kk * 8 + c];
        qf[kk][1] = Qs_u[(rowA + 8) * SDIM + kk * 8 + c];
        qf[kk][2] = Qs_u[rowA * SDIM + kk * 8 + c + 4];
        qf[kk][3] = Qs_u[(rowA + 8) * SDIM + kk * 8 + c + 4];
    }

    float mA = -1e30f, mB = -1e30f, lA = 0.f, lB = 0.f;
    float o[8][4];
#pragma unroll
    for (int nf = 0; nf < 8; nf++)
#pragma unroll
        for (int j = 0; j < 4; j++) o[nf][j] = 0.f;

    const int kt_end = min(ch * 8 + 8, qt + 1);
    for (int kt = ch * 8; kt < kt_end; kt++) {
        const int k0 = kt * 64;
        __syncthreads();
        for (int i = tid; i < 64 * 16; i += 128) {
            int key = i >> 4, c4 = (i & 15) * 4;
            *(float4*)&Ks[key * SDIM + c4] =
                *(const float4*)&g_k[base + (size_t)(k0 + key) * HH + c4];
        }
        for (int i = tid; i < 64 * 16; i += 128) {
            int key = i & 63, h4 = (i >> 6) * 4;
            float4 vv = *(const float4*)&g_v[base + (size_t)(k0 + key) * HH + h4];
            Vt[(h4 + 0) * SDIM + key] = vv.x;
            Vt[(h4 + 1) * SDIM + key] = vv.y;
            Vt[(h4 + 2) * SDIM + key] = vv.z;
            Vt[(h4 + 3) * SDIM + key] = vv.w;
        }
        __syncthreads();

        float s[8][4];
#pragma unroll
        for (int nf = 0; nf < 8; nf++) {
#pragma unroll
            for (int j = 0; j < 4; j++) s[nf][j] = 0.f;
#pragma unroll
            for (int kk = 0; kk < 8; kk++) {
                uint32_t b0 = Ks_u[(nf * 8 + r) * SDIM + kk * 8 + c];
                uint32_t b1 = Ks_u[(nf * 8 + r) * SDIM + kk * 8 + c + 4];
                mma_tf32(s[nf], qf[kk], b0, b1);
            }
        }

        if (kt == qt) {
            int gA = q0 + rowA;
#pragma unroll
            for (int nf = 0; nf < 8; nf++) {
                int col = k0 + nf * 8 + 2 * c;
                if (col > gA)     s[nf][0] = -1e30f;
                if (col + 1 > gA) s[nf][1] = -1e30f;
                if (col > gA + 8)     s[nf][2] = -1e30f;
                if (col + 1 > gA + 8) s[nf][3] = -1e30f;
            }
        }

        float xA = -1e30f, xB = -1e30f;
#pragma unroll
        for (int nf = 0; nf < 8; nf++) {
            xA = fmaxf(xA, fmaxf(s[nf][0], s[nf][1]));
            xB = fmaxf(xB, fmaxf(s[nf][2], s[nf][3]));
        }
#pragma unroll
        for (int d = 1; d < 4; d <<= 1) {
            xA = fmaxf(xA, __shfl_xor_sync(0xffffffffu, xA, d));
            xB = fmaxf(xB, __shfl_xor_sync(0xffffffffu, xB, d));
        }
        float mnA = fmaxf(mA, xA), mnB = fmaxf(mB, xB);
        float aA = __expf(mA - mnA), aB = __expf(mB - mnB);

        float sumA = 0.f, sumB = 0.f;
#pragma unroll
        for (int nf = 0; nf < 8; nf++) {
            float p0 = __expf(s[nf][0] - mnA);
            float p1 = __expf(s[nf][1] - mnA);
            float p2 = __expf(s[nf][2] - mnB);
            float p3 = __expf(s[nf][3] - mnB);
            sumA += p0 + p1;
            sumB += p2 + p3;
            int colo = nf * 8 + 2 * c;
            *(float2*)&Ps[rowA * SDIM + colo] = make_float2(tf32r(p0), tf32r(p1));
            *(float2*)&Ps[(rowA + 8) * SDIM + colo] = make_float2(tf32r(p2), tf32r(p3));
        }
#pragma unroll
        for (int d = 1; d < 4; d <<= 1) {
            sumA += __shfl_xor_sync(0xffffffffu, sumA, d);
            sumB += __shfl_xor_sync(0xffffffffu, sumB, d);
        }
        lA = lA * aA + sumA;
        lB = lB * aB + sumB;
        mA = mnA;
        mB = mnB;
#pragma unroll
        for (int nf = 0; nf < 8; nf++) {
            o[nf][0] *= aA; o[nf][1] *= aA;
            o[nf][2] *= aB; o[nf][3] *= aB;
        }
        __syncthreads();

#pragma unroll
        for (int kk = 0; kk < 8; kk++) {
            uint32_t a[4];
            a[0] = Ps_u[rowA * SDIM + kk * 8 + c];
            a[1] = Ps_u[(rowA + 8) * SDIM + kk * 8 + c];
            a[2] = Ps_u[rowA * SDIM + kk * 8 + c + 4];
            a[3] = Ps_u[(rowA + 8) * SDIM + kk * 8 + c + 4];
#pragma unroll
            for (int nf = 0; nf < 8; nf++) {
                uint32_t b0 = Vt_u[(nf * 8 + r) * SDIM + kk * 8 + c];
                uint32_t b1 = Vt_u[(nf * 8 + r) * SDIM + kk * 8 + c + 4];
                mma_tf32(o[nf], a, b0, b1);
            }
        }
    }

#pragma unroll
    for (int nf = 0; nf < 8; nf++) {
        int colo = nf * 8 + 2 * c;
        *(float2*)&g_opart[(size_t)unit * 4096 + rowA * 64 + colo] =
            make_float2(o[nf][0], o[nf][1]);
        *(float2*)&g_opart[(size_t)unit * 4096 + (rowA + 8) * 64 + colo] =
            make_float2(o[nf][2], o[nf][3]);
    }
    if (c == 0) {
        g_mpart[unit * 64 + rowA] = mA;
        g_mpart[unit * 64 + rowA + 8] = mB;
        g_lpart[unit * 64 + rowA] = lA;
        g_lpart[unit * 64 + rowA + 8] = lB;
    }
}

// ---------------------------------------------------------------------------
// Combine (unchanged from R3)
// ---------------------------------------------------------------------------
__global__ __launch_bounds__(128) void attn_combine(float* __restrict__ out)
{
    const int qt = blockIdx.x, b = blockIdx.y;
    const int tid = threadIdx.x;
    const int row = tid >> 1;
    const int half = tid & 1;
    const int nch = (qt >> 3) + 1;
    const int ubase = (b * 64 + qt) * 8;

    float M = -1e30f;
    for (int i = 0; i < nch; i++)
        M = fmaxf(M, g_mpart[(ubase + i) * 64 + row]);

    float L = 0.f;
    float acc[32];
#pragma unroll
    for (int j = 0; j < 32; j++) acc[j] = 0.f;

    for (int i = 0; i < nch; i++) {
        float coef = __expf(g_mpart[(ubase + i) * 64 + row] - M);
        L += coef * g_lpart[(ubase + i) * 64 + row];
        const float* src = &g_opart[(size_t)(ubase + i) * 4096 + row * 64 + half * 32];
#pragma unroll
        for (int j = 0; j < 8; j++) {
            float4 v = *(const float4*)&src[4 * j];
            acc[4 * j + 0] += coef * v.x;
            acc[4 * j + 1] += coef * v.y;
            acc[4 * j + 2] += coef * v.z;
            acc[4 * j + 3] += coef * v.w;
        }
    }

    float inv = 1.f / L;
    float* dst = &out[(size_t)b * TT * HH + (size_t)(qt * 64 + row) * HH + half * 32];
#pragma unroll
    for (int j = 0; j < 8; j++) {
        float4 v = make_float4(acc[4 * j] * inv, acc[4 * j + 1] * inv,
                               acc[4 * j + 2] * inv, acc[4 * j + 3] * inv);
        *(float4*)&dst[4 * j] = v;
    }
}

// ---------------------------------------------------------------------------
extern "C" void kernel_launch(void* const* d_in, const int* in_sizes, int n_in,
                              void* d_out, int out_size)
{
    const float* x  = (const float*)d_in[0];
    const float* Wk = (const float*)d_in[1];
    const float* Wq = (const float*)d_in[2];
    const float* Wv = (const float*)d_in[3];
    float* out = (float*)d_out;

    const int smem_attn = 3 * 64 * SDIM * (int)sizeof(float);

    cudaFuncSetAttribute(proj_mma, cudaFuncAttributeMaxDynamicSharedMemorySize, PSMEM);
    cudaFuncSetAttribute(attn_partial, cudaFuncAttributeMaxDynamicSharedMemorySize, smem_attn);

    wt_kernel<<<384, 256>>>(Wk, Wq, Wv);
    proj_mma<<<128, 256, PSMEM>>>(x);
    attn_partial<<<dim3(8, 64, BB), 128, smem_attn>>>();
    attn_combine<<<dim3(64, BB), 128>>>(out);
}

// round 5
// speedup vs baseline: 5.3273x; 1.0249x over previous
#include <cuda_runtime.h>
#include <cstdint>

#define BB 4
#define TT 4096
#define CC 512
#define HH 64
#define SCALE 0.044194173824159216f   // 512^-0.5
#define CH 8                           // k-tiles (64 keys) per split-K chunk

// projected q (pre-scaled), k, v — tf32-rounded fp32
__device__ float g_q[BB * TT * HH];
__device__ float g_k[BB * TT * HH];
__device__ float g_v[BB * TT * HH];
// W transposed, tf32 hi/lo interleaved: [192 n][512 k][2]
__device__ float2 g_wt2[192 * 512];
// split-K partials: 4 b x 32 qtiles x 8 chunks = 1024 units, 128 rows each
__device__ float g_opart[1024 * 128 * 64];
__device__ float g_mpart[1024 * 128];
__device__ float g_lpart[1024 * 128];

__device__ __forceinline__ float tf32r(float x) {
    uint32_t t;
    asm("cvt.rna.tf32.f32 %0, %1;" : "=r"(t) : "f"(x));
    return __uint_as_float(t);
}
__device__ __forceinline__ uint32_t tf32u(float x) {
    uint32_t t;
    asm("cvt.rna.tf32.f32 %0, %1;" : "=r"(t) : "f"(x));
    return t;
}

__device__ __forceinline__ void mma_tf32(float* d, const uint32_t* a,
                                         uint32_t b0, uint32_t b1) {
    asm volatile(
        "mma.sync.aligned.m16n8k8.row.col.f32.tf32.tf32.f32 "
        "{%0,%1,%2,%3}, {%4,%5,%6,%7}, {%8,%9}, {%0,%1,%2,%3};"
        : "+f"(d[0]), "+f"(d[1]), "+f"(d[2]), "+f"(d[3])
        : "r"(a[0]), "r"(a[1]), "r"(a[2]), "r"(a[3]), "r"(b0), "r"(b1));
}

// ---------------------------------------------------------------------------
// W transpose + tf32 hi/lo split, interleaved
// ---------------------------------------------------------------------------
__global__ __launch_bounds__(256) void wt_kernel(
    const float* __restrict__ Wk,
    const float* __restrict__ Wq,
    const float* __restrict__ Wv)
{
    int idx = blockIdx.x * 256 + threadIdx.x;   // 384 x 256 = 98304
    int k = idx / 192, n = idx - k * 192;
    const float* W = (n < 64) ? Wk : (n < 128) ? Wq : Wv;
    float w = W[k * HH + (n & 63)];
    float hi = tf32r(w);
    g_wt2[n * CC + k] = make_float2(hi, tf32r(w - hi));
}

// ---------------------------------------------------------------------------
// Projection on HMMA tf32 (3-term emulated fp32), no smem: direct LDG frags.
// CTA 256 thr (8 warps): tile M=128 x N=192. Warp (mw,nw): 64x48 warp tile.
// ---------------------------------------------------------------------------
__global__ __launch_bounds__(256) void proj_mma(const float* __restrict__ x)
{
    const int tid = threadIdx.x;
    const int w = tid >> 5;
    const int lane = tid & 31;
    const int gr = lane >> 2;
    const int gc = lane & 3;
    const int mw = w >> 2, nw = w & 3;
    const int row0 = blockIdx.x * 128;

    float acc[4][6][4];
#pragma unroll
    for (int mf = 0; mf < 4; mf++)
#pragma unroll
        for (int nf = 0; nf < 6; nf++)
#pragma unroll
            for (int j = 0; j < 4; j++) acc[mf][nf][j] = 0.f;

#pragma unroll 2
    for (int ck = 0; ck < 16; ck++) {
        const int k0 = ck * 32;
#pragma unroll
        for (int kk = 0; kk < 4; kk++) {
            const int kb = k0 + kk * 8 + gc;
            uint32_t ah[4][4], al[4][4];
#pragma unroll
            for (int mf = 0; mf < 4; mf++) {
                int rb = row0 + 64 * mw + 16 * mf + gr;
                float x0 = x[(size_t)rb * CC + kb];
                float x1 = x[(size_t)(rb + 8) * CC + kb];
                float x2 = x[(size_t)rb * CC + kb + 4];
                float x3 = x[(size_t)(rb + 8) * CC + kb + 4];
                ah[mf][0] = tf32u(x0);
                ah[mf][1] = tf32u(x1);
                ah[mf][2] = tf32u(x2);
                ah[mf][3] = tf32u(x3);
                al[mf][0] = tf32u(x0 - __uint_as_float(ah[mf][0]));
                al[mf][1] = tf32u(x1 - __uint_as_float(ah[mf][1]));
                al[mf][2] = tf32u(x2 - __uint_as_float(ah[mf][2]));
                al[mf][3] = tf32u(x3 - __uint_as_float(ah[mf][3]));
            }
#pragma unroll
            for (int nf = 0; nf < 6; nf++) {
                int nr = 48 * nw + 8 * nf + gr;
                float2 w0 = g_wt2[nr * CC + kb];
                float2 w1 = g_wt2[nr * CC + kb + 4];
                uint32_t bh0 = __float_as_uint(w0.x);
                uint32_t bl0 = __float_as_uint(w0.y);
                uint32_t bh1 = __float_as_uint(w1.x);
                uint32_t bl1 = __float_as_uint(w1.y);
#pragma unroll
                for (int mf = 0; mf < 4; mf++) {
                    mma_tf32(acc[mf][nf], ah[mf], bh0, bh1);
                    mma_tf32(acc[mf][nf], ah[mf], bl0, bl1);
                    mma_tf32(acc[mf][nf], al[mf], bh0, bh1);
                }
            }
        }
    }

    // epilogue: scale q, round to tf32, scatter
#pragma unroll
    for (int mf = 0; mf < 4; mf++) {
#pragma unroll
        for (int nf = 0; nf < 6; nf++) {
            int n = 48 * nw + 8 * nf + 2 * gc;
            float* dst = (n < 64) ? g_k : (n < 128) ? g_q : g_v;
            float f = (n >= 64 && n < 128) ? SCALE : 1.0f;
            int r0 = row0 + 64 * mw + 16 * mf + gr;
            *(float2*)&dst[(size_t)r0 * HH + (n & 63)] =
                make_float2(tf32r(acc[mf][nf][0] * f), tf32r(acc[mf][nf][1] * f));
            *(float2*)&dst[(size_t)(r0 + 8) * HH + (n & 63)] =
                make_float2(tf32r(acc[mf][nf][2] * f), tf32r(acc[mf][nf][3] * f));
        }
    }
}

// ---------------------------------------------------------------------------
// Split-K flash attention partial. CTA = 256 thr (8 warps), Q tile 128 rows;
// warp w owns rows 16w..16w+15. Chunk = up to 8 k-tiles of 64 keys.
// smem (floats): Q[128][68], P[128][72], K[64][68], V[64][72]
// ---------------------------------------------------------------------------
#define QSD 68
#define PSD 72
#define KSD 68
#define VSD 72
#define OFF_P (128 * QSD)
#define OFF_K (OFF_P + 128 * PSD)
#define OFF_V (OFF_K + 64 * KSD)
#define ATTN_SMEM ((OFF_V + 64 * VSD) * 4)

__global__ __launch_bounds__(256) void attn_partial()
{
    const int ch = blockIdx.x, qt = blockIdx.y, b = blockIdx.z;
    const int nkt = 2 * qt + 2;
    if (ch * CH >= nkt) return;

    extern __shared__ float sm[];
    float* Qs = sm;
    float* Ps = sm + OFF_P;
    float* Ks = sm + OFF_K;
    float* Vs = sm + OFF_V;
    uint32_t* Qs_u = (uint32_t*)Qs;
    uint32_t* Ps_u = (uint32_t*)Ps;
    uint32_t* Ks_u = (uint32_t*)Ks;
    uint32_t* Vs_u = (uint32_t*)Vs;

    const int tid = threadIdx.x;
    const int w = tid >> 5;
    const int lane = tid & 31;
    const int r = lane >> 2;
    const int c = lane & 3;
    const int rowA = 16 * w + r;
    const int q0 = qt * 128;
    const size_t base = (size_t)b * TT * HH;
    const int unit = (b * 32 + qt) * 8 + ch;

    // Q tile [128 x 64] -> smem
    for (int i = tid; i < 128 * 16; i += 256) {
        int row = i >> 4, c4 = (i & 15) * 4;
        *(float4*)&Qs[row * QSD + c4] =
            *(const float4*)&g_q[base + (size_t)(q0 + row) * HH + c4];
    }

    float mA = -1e30f, mB = -1e30f, lA = 0.f, lB = 0.f;
    float o[8][4];
#pragma unroll
    for (int nf = 0; nf < 8; nf++)
#pragma unroll
        for (int j = 0; j < 4; j++) o[nf][j] = 0.f;

    const int kt_end = min(ch * CH + CH, nkt);
    for (int kt = ch * CH; kt < kt_end; kt++) {
        const int k0 = kt * 64;
        __syncthreads();   // K/V overwrite safe; Q visible on first iter
        for (int i = tid; i < 64 * 16; i += 256) {
            int key = i >> 4, c4 = (i & 15) * 4;
            *(float4*)&Ks[key * KSD + c4] =
                *(const float4*)&g_k[base + (size_t)(k0 + key) * HH + c4];
        }
        for (int i = tid; i < 64 * 16; i += 256) {
            int key = i >> 4, c4 = (i & 15) * 4;
            *(float4*)&Vs[key * VSD + c4] =
                *(const float4*)&g_v[base + (size_t)(k0 + key) * HH + c4];
        }
        __syncthreads();

        // S = Q K^T  (16 rows x 64 keys per warp)
        float s[8][4];
#pragma unroll
        for (int nf = 0; nf < 8; nf++)
#pragma unroll
            for (int j = 0; j < 4; j++) s[nf][j] = 0.f;
#pragma unroll
        for (int kk = 0; kk < 8; kk++) {
            uint32_t a[4];
            a[0] = Qs_u[rowA * QSD + kk * 8 + c];
            a[1] = Qs_u[(rowA + 8) * QSD + kk * 8 + c];
            a[2] = Qs_u[rowA * QSD + kk * 8 + c + 4];
            a[3] = Qs_u[(rowA + 8) * QSD + kk * 8 + c + 4];
#pragma unroll
            for (int nf = 0; nf < 8; nf++) {
                uint32_t b0 = Ks_u[(nf * 8 + r) * KSD + kk * 8 + c];
                uint32_t b1 = Ks_u[(nf * 8 + r) * KSD + kk * 8 + c + 4];
                mma_tf32(s[nf], a, b0, b1);
            }
        }

        // causal mask (only the last two k-tiles of this q-tile's range)
        if (kt >= nkt - 2) {
            int gA = q0 + rowA;
#pragma unroll
            for (int nf = 0; nf < 8; nf++) {
                int col = k0 + nf * 8 + 2 * c;
                if (col > gA)     s[nf][0] = -1e30f;
                if (col + 1 > gA) s[nf][1] = -1e30f;
                if (col > gA + 8)     s[nf][2] = -1e30f;
                if (col + 1 > gA + 8) s[nf][3] = -1e30f;
            }
        }

        // online softmax (rows rowA / rowA+8); reduce over 4 c-lanes
        float xA = -1e30f, xB = -1e30f;
#pragma unroll
        for (int nf = 0; nf < 8; nf++) {
            xA = fmaxf(xA, fmaxf(s[nf][0], s[nf][1]));
            xB = fmaxf(xB, fmaxf(s[nf][2], s[nf][3]));
        }
#pragma unroll
        for (int d = 1; d < 4; d <<= 1) {
            xA = fmaxf(xA, __shfl_xor_sync(0xffffffffu, xA, d));
            xB = fmaxf(xB, __shfl_xor_sync(0xffffffffu, xB, d));
        }
        float mnA = fmaxf(mA, xA), mnB = fmaxf(mB, xB);
        float aA = __expf(mA - mnA), aB = __expf(mB - mnB);

        float sumA = 0.f, sumB = 0.f;
#pragma unroll
        for (int nf = 0; nf < 8; nf++) {
            float p0 = __expf(s[nf][0] - mnA);
            float p1 = __expf(s[nf][1] - mnA);
            float p2 = __expf(s[nf][2] - mnB);
            float p3 = __expf(s[nf][3] - mnB);
            sumA += p0 + p1;
            sumB += p2 + p3;
            int colo = nf * 8 + 2 * c;
            *(float2*)&Ps[rowA * PSD + colo] = make_float2(tf32r(p0), tf32r(p1));
            *(float2*)&Ps[(rowA + 8) * PSD + colo] = make_float2(tf32r(p2), tf32r(p3));
        }
#pragma unroll
        for (int d = 1; d < 4; d <<= 1) {
            sumA += __shfl_xor_sync(0xffffffffu, sumA, d);
            sumB += __shfl_xor_sync(0xffffffffu, sumB, d);
        }
        lA = lA * aA + sumA;
        lB = lB * aB + sumB;
        mA = mnA;
        mB = mnB;
#pragma unroll
        for (int nf = 0; nf < 8; nf++) {
            o[nf][0] *= aA; o[nf][1] *= aA;
            o[nf][2] *= aB; o[nf][3] *= aB;
        }
        __syncwarp();   // P rows are warp-private; warp-level visibility suffices

        // O += P V  (V in natural [key][h] layout)
#pragma unroll
        for (int kk = 0; kk < 8; kk++) {
            uint32_t a[4];
            a[0] = Ps_u[rowA * PSD + kk * 8 + c];
            a[1] = Ps_u[(rowA + 8) * PSD + kk * 8 + c];
            a[2] = Ps_u[rowA * PSD + kk * 8 + c + 4];
            a[3] = Ps_u[(rowA + 8) * PSD + kk * 8 + c + 4];
#pragma unroll
            for (int nf = 0; nf < 8; nf++) {
                uint32_t b0 = Vs_u[(kk * 8 + c) * VSD + nf * 8 + r];
                uint32_t b1 = Vs_u[(kk * 8 + c + 4) * VSD + nf * 8 + r];
                mma_tf32(o[nf], a, b0, b1);
            }
        }
    }

    // write partial O (unnormalized) + per-row m, l
#pragma unroll
    for (int nf = 0; nf < 8; nf++) {
        int colo = nf * 8 + 2 * c;
        *(float2*)&g_opart[(size_t)unit * 8192 + rowA * 64 + colo] =
            make_float2(o[nf][0], o[nf][1]);
        *(float2*)&g_opart[(size_t)unit * 8192 + (rowA + 8) * 64 + colo] =
            make_float2(o[nf][2], o[nf][3]);
    }
    if (c == 0) {
        g_mpart[unit * 128 + rowA] = mA;
        g_mpart[unit * 128 + rowA + 8] = mB;
        g_lpart[unit * 128 + rowA] = lA;
        g_lpart[unit * 128 + rowA + 8] = lB;
    }
}

// ---------------------------------------------------------------------------
// Combine: LSE-merge up to 8 chunk partials per (b, 128-row qtile).
// 256 thr: row = tid>>1 (128 rows), half = tid&1 (32 cols each).
// ---------------------------------------------------------------------------
__global__ __launch_bounds__(256) void attn_combine(float* __restrict__ out)
{
    const int qt = blockIdx.x, b = blockIdx.y;
    const int tid = threadIdx.x;
    const int row = tid >> 1;
    const int half = tid & 1;
    const int nch = (2 * qt + 2 + CH - 1) / CH;
    const int ubase = (b * 32 + qt) * 8;

    float M = -1e30f;
    for (int i = 0; i < nch; i++)
        M = fmaxf(M, g_mpart[(ubase + i) * 128 + row]);

    float L = 0.f;
    float acc[32];
#pragma unroll
    for (int j = 0; j < 32; j++) acc[j] = 0.f;

    for (int i = 0; i < nch; i++) {
        float coef = __expf(g_mpart[(ubase + i) * 128 + row] - M);
        L += coef * g_lpart[(ubase + i) * 128 + row];
        const float* src =
            &g_opart[(size_t)(ubase + i) * 8192 + row * 64 + half * 32];
#pragma unroll
        for (int j = 0; j < 8; j++) {
            float4 v = *(const float4*)&src[4 * j];
            acc[4 * j + 0] += coef * v.x;
            acc[4 * j + 1] += coef * v.y;
            acc[4 * j + 2] += coef * v.z;
            acc[4 * j + 3] += coef * v.w;
        }
    }

    float inv = 1.f / L;
    float* dst = &out[(size_t)b * TT * HH + (size_t)(qt * 128 + row) * HH + half * 32];
#pragma unroll
    for (int j = 0; j < 8; j++) {
        float4 v = make_float4(acc[4 * j] * inv, acc[4 * j + 1] * inv,
                               acc[4 * j + 2] * inv, acc[4 * j + 3] * inv);
        *(float4*)&dst[4 * j] = v;
    }
}

// ---------------------------------------------------------------------------
extern "C" void kernel_launch(void* const* d_in, const int* in_sizes, int n_in,
                              void* d_out, int out_size)
{
    const float* x  = (const float*)d_in[0];
    const float* Wk = (const float*)d_in[1];
    const float* Wq = (const float*)d_in[2];
    const float* Wv = (const float*)d_in[3];
    float* out = (float*)d_out;

    cudaFuncSetAttribute(attn_partial, cudaFuncAttributeMaxDynamicSharedMemorySize, ATTN_SMEM);

    wt_kernel<<<384, 256>>>(Wk, Wq, Wv);
    proj_mma<<<128, 256>>>(x);
    attn_partial<<<dim3(8, 32, BB), 256, ATTN_SMEM>>>();
    attn_combine<<<dim3(32, BB), 256>>>(out);
}

// round 6
// speedup vs baseline: 5.3524x; 1.0047x over previous
#include <cuda_runtime.h>
#include <cstdint>

#define BB 4
#define TT 4096
#define CC 512
#define HH 64
#define SCALE 0.044194173824159216f   // 512^-0.5
#define CH 8                           // k-tiles (64 keys) per split-K chunk

// projected q (pre-scaled), k, v — tf32-rounded fp32
__device__ float g_q[BB * TT * HH];
__device__ float g_k[BB * TT * HH];
__device__ float g_v[BB * TT * HH];
// W transposed, tf32 hi/lo interleaved: [192 n][512 k][2]
__device__ float2 g_wt2[192 * 512];
// split-K partials: 4 b x 32 qtiles x 8 chunks = 1024 units, 128 rows each
__device__ float g_opart[1024 * 128 * 64];
__device__ float g_mpart[1024 * 128];
__device__ float g_lpart[1024 * 128];

__device__ __forceinline__ float tf32r(float x) {
    uint32_t t;
    asm("cvt.rna.tf32.f32 %0, %1;" : "=r"(t) : "f"(x));
    return __uint_as_float(t);
}
__device__ __forceinline__ uint32_t tf32u(float x) {
    uint32_t t;
    asm("cvt.rna.tf32.f32 %0, %1;" : "=r"(t) : "f"(x));
    return t;
}

__device__ __forceinline__ void mma_tf32(float* d, const uint32_t* a,
                                         uint32_t b0, uint32_t b1) {
    asm volatile(
        "mma.sync.aligned.m16n8k8.row.col.f32.tf32.tf32.f32 "
        "{%0,%1,%2,%3}, {%4,%5,%6,%7}, {%8,%9}, {%0,%1,%2,%3};"
        : "+f"(d[0]), "+f"(d[1]), "+f"(d[2]), "+f"(d[3])
        : "r"(a[0]), "r"(a[1]), "r"(a[2]), "r"(a[3]), "r"(b0), "r"(b1));
}

// ---------------------------------------------------------------------------
// W transpose + tf32 hi/lo split, interleaved
// ---------------------------------------------------------------------------
__global__ __launch_bounds__(256) void wt_kernel(
    const float* __restrict__ Wk,
    const float* __restrict__ Wq,
    const float* __restrict__ Wv)
{
    int idx = blockIdx.x * 256 + threadIdx.x;   // 384 x 256 = 98304
    int k = idx / 192, n = idx - k * 192;
    const float* W = (n < 64) ? Wk : (n < 128) ? Wq : Wv;
    float w = W[k * HH + (n & 63)];
    float hi = tf32r(w);
    g_wt2[n * CC + k] = make_float2(hi, tf32r(w - hi));
}

// ---------------------------------------------------------------------------
// Projection on HMMA tf32 (3-term emulated fp32), direct LDG frags.
// CTA 256 thr (8 warps): tile M=64 x N=192, grid 256 for latency hiding.
// Warp (mw = w>>2 in 0..1, nw = w&3): 32x48 warp tile (2 mf x 6 nf).
// ---------------------------------------------------------------------------
__global__ __launch_bounds__(256) void proj_mma(const float* __restrict__ x)
{
    const int tid = threadIdx.x;
    const int w = tid >> 5;
    const int lane = tid & 31;
    const int gr = lane >> 2;
    const int gc = lane & 3;
    const int mw = w >> 2, nw = w & 3;
    const int row0 = blockIdx.x * 64;

    float acc[2][6][4];
#pragma unroll
    for (int mf = 0; mf < 2; mf++)
#pragma unroll
        for (int nf = 0; nf < 6; nf++)
#pragma unroll
            for (int j = 0; j < 4; j++) acc[mf][nf][j] = 0.f;

#pragma unroll 2
    for (int ck = 0; ck < 16; ck++) {
        const int k0 = ck * 32;
#pragma unroll
        for (int kk = 0; kk < 4; kk++) {
            const int kb = k0 + kk * 8 + gc;
            uint32_t ah[2][4], al[2][4];
#pragma unroll
            for (int mf = 0; mf < 2; mf++) {
                int rb = row0 + 32 * mw + 16 * mf + gr;
                float x0 = x[(size_t)rb * CC + kb];
                float x1 = x[(size_t)(rb + 8) * CC + kb];
                float x2 = x[(size_t)rb * CC + kb + 4];
                float x3 = x[(size_t)(rb + 8) * CC + kb + 4];
                ah[mf][0] = tf32u(x0);
                ah[mf][1] = tf32u(x1);
                ah[mf][2] = tf32u(x2);
                ah[mf][3] = tf32u(x3);
                al[mf][0] = tf32u(x0 - __uint_as_float(ah[mf][0]));
                al[mf][1] = tf32u(x1 - __uint_as_float(ah[mf][1]));
                al[mf][2] = tf32u(x2 - __uint_as_float(ah[mf][2]));
                al[mf][3] = tf32u(x3 - __uint_as_float(ah[mf][3]));
            }
#pragma unroll
            for (int nf = 0; nf < 6; nf++) {
                int nr = 48 * nw + 8 * nf + gr;
                float2 w0 = g_wt2[nr * CC + kb];
                float2 w1 = g_wt2[nr * CC + kb + 4];
                uint32_t bh0 = __float_as_uint(w0.x);
                uint32_t bl0 = __float_as_uint(w0.y);
                uint32_t bh1 = __float_as_uint(w1.x);
                uint32_t bl1 = __float_as_uint(w1.y);
#pragma unroll
                for (int mf = 0; mf < 2; mf++) {
                    mma_tf32(acc[mf][nf], ah[mf], bh0, bh1);
                    mma_tf32(acc[mf][nf], ah[mf], bl0, bl1);
                    mma_tf32(acc[mf][nf], al[mf], bh0, bh1);
                }
            }
        }
    }

    // epilogue: scale q, round to tf32, scatter
#pragma unroll
    for (int mf = 0; mf < 2; mf++) {
#pragma unroll
        for (int nf = 0; nf < 6; nf++) {
            int n = 48 * nw + 8 * nf + 2 * gc;
            float* dst = (n < 64) ? g_k : (n < 128) ? g_q : g_v;
            float f = (n >= 64 && n < 128) ? SCALE : 1.0f;
            int r0 = row0 + 32 * mw + 16 * mf + gr;
            *(float2*)&dst[(size_t)r0 * HH + (n & 63)] =
                make_float2(tf32r(acc[mf][nf][0] * f), tf32r(acc[mf][nf][1] * f));
            *(float2*)&dst[(size_t)(r0 + 8) * HH + (n & 63)] =
                make_float2(tf32r(acc[mf][nf][2] * f), tf32r(acc[mf][nf][3] * f));
        }
    }
}

// ---------------------------------------------------------------------------
// Split-K flash attention partial. CTA = 128 thr (4 warps), Q tile 128 rows;
// warp w owns rows 32w..32w+31 (2 m-frags) — B-frags amortized over 2 MMAs.
// smem (floats): Q[128][68], P[128][72], K[64][68], V[64][72] = 105 KB.
// ---------------------------------------------------------------------------
#define QSD 68
#define PSD 72
#define KSD 68
#define VSD 72
#define OFF_P (128 * QSD)
#define OFF_K (OFF_P + 128 * PSD)
#define OFF_V (OFF_K + 64 * KSD)
#define ATTN_SMEM ((OFF_V + 64 * VSD) * 4)

__global__ __launch_bounds__(128) void attn_partial()
{
    const int ch = blockIdx.x, qt = blockIdx.y, b = blockIdx.z;
    const int nkt = 2 * qt + 2;
    if (ch * CH >= nkt) return;

    extern __shared__ float sm[];
    float* Qs = sm;
    float* Ps = sm + OFF_P;
    float* Ks = sm + OFF_K;
    float* Vs = sm + OFF_V;
    uint32_t* Qs_u = (uint32_t*)Qs;
    uint32_t* Ps_u = (uint32_t*)Ps;
    uint32_t* Ks_u = (uint32_t*)Ks;
    uint32_t* Vs_u = (uint32_t*)Vs;

    const int tid = threadIdx.x;
    const int w = tid >> 5;
    const int lane = tid & 31;
    const int r = lane >> 2;
    const int c = lane & 3;
    const int rowW = 32 * w;            // warp row base
    const int q0 = qt * 128;
    const size_t base = (size_t)b * TT * HH;
    const int unit = (b * 32 + qt) * 8 + ch;

    // Q tile [128 x 64] -> smem
    for (int i = tid; i < 128 * 16; i += 128) {
        int row = i >> 4, c4 = (i & 15) * 4;
        *(float4*)&Qs[row * QSD + c4] =
            *(const float4*)&g_q[base + (size_t)(q0 + row) * HH + c4];
    }

    float m[2][2], l[2][2];
#pragma unroll
    for (int mf = 0; mf < 2; mf++) {
        m[mf][0] = m[mf][1] = -1e30f;
        l[mf][0] = l[mf][1] = 0.f;
    }
    float o[2][8][4];
#pragma unroll
    for (int mf = 0; mf < 2; mf++)
#pragma unroll
        for (int nf = 0; nf < 8; nf++)
#pragma unroll
            for (int j = 0; j < 4; j++) o[mf][nf][j] = 0.f;

    const int kt_end = min(ch * CH + CH, nkt);
    for (int kt = ch * CH; kt < kt_end; kt++) {
        const int k0 = kt * 64;
        __syncthreads();
        for (int i = tid; i < 64 * 16; i += 128) {
            int key = i >> 4, c4 = (i & 15) * 4;
            *(float4*)&Ks[key * KSD + c4] =
                *(const float4*)&g_k[base + (size_t)(k0 + key) * HH + c4];
        }
        for (int i = tid; i < 64 * 16; i += 128) {
            int key = i >> 4, c4 = (i & 15) * 4;
            *(float4*)&Vs[key * VSD + c4] =
                *(const float4*)&g_v[base + (size_t)(k0 + key) * HH + c4];
        }
        __syncthreads();

        // S = Q K^T  (32 rows x 64 keys per warp; B-frags shared by 2 mf)
        float s[2][8][4];
#pragma unroll
        for (int mf = 0; mf < 2; mf++)
#pragma unroll
            for (int nf = 0; nf < 8; nf++)
#pragma unroll
                for (int j = 0; j < 4; j++) s[mf][nf][j] = 0.f;
#pragma unroll
        for (int kk = 0; kk < 8; kk++) {
            uint32_t a[2][4];
#pragma unroll
            for (int mf = 0; mf < 2; mf++) {
                int rb = rowW + 16 * mf + r;
                a[mf][0] = Qs_u[rb * QSD + kk * 8 + c];
                a[mf][1] = Qs_u[(rb + 8) * QSD + kk * 8 + c];
                a[mf][2] = Qs_u[rb * QSD + kk * 8 + c + 4];
                a[mf][3] = Qs_u[(rb + 8) * QSD + kk * 8 + c + 4];
            }
#pragma unroll
            for (int nf = 0; nf < 8; nf++) {
                uint32_t b0 = Ks_u[(nf * 8 + r) * KSD + kk * 8 + c];
                uint32_t b1 = Ks_u[(nf * 8 + r) * KSD + kk * 8 + c + 4];
                mma_tf32(s[0][nf], a[0], b0, b1);
                mma_tf32(s[1][nf], a[1], b0, b1);
            }
        }

        // causal mask (only last two k-tiles of this q-tile's range)
        if (kt >= nkt - 2) {
#pragma unroll
            for (int mf = 0; mf < 2; mf++) {
                int gA = q0 + rowW + 16 * mf + r;
#pragma unroll
                for (int nf = 0; nf < 8; nf++) {
                    int col = k0 + nf * 8 + 2 * c;
                    if (col > gA)     s[mf][nf][0] = -1e30f;
                    if (col + 1 > gA) s[mf][nf][1] = -1e30f;
                    if (col > gA + 8)     s[mf][nf][2] = -1e30f;
                    if (col + 1 > gA + 8) s[mf][nf][3] = -1e30f;
                }
            }
        }

        // online softmax per mf (rows rb / rb+8); reduce over 4 c-lanes
#pragma unroll
        for (int mf = 0; mf < 2; mf++) {
            float xA = -1e30f, xB = -1e30f;
#pragma unroll
            for (int nf = 0; nf < 8; nf++) {
                xA = fmaxf(xA, fmaxf(s[mf][nf][0], s[mf][nf][1]));
                xB = fmaxf(xB, fmaxf(s[mf][nf][2], s[mf][nf][3]));
            }
#pragma unroll
            for (int d = 1; d < 4; d <<= 1) {
                xA = fmaxf(xA, __shfl_xor_sync(0xffffffffu, xA, d));
                xB = fmaxf(xB, __shfl_xor_sync(0xffffffffu, xB, d));
            }
            float mnA = fmaxf(m[mf][0], xA), mnB = fmaxf(m[mf][1], xB);
            float aA = __expf(m[mf][0] - mnA), aB = __expf(m[mf][1] - mnB);

            int rb = rowW + 16 * mf + r;
            float sumA = 0.f, sumB = 0.f;
#pragma unroll
            for (int nf = 0; nf < 8; nf++) {
                float p0 = __expf(s[mf][nf][0] - mnA);
                float p1 = __expf(s[mf][nf][1] - mnA);
                float p2 = __expf(s[mf][nf][2] - mnB);
                float p3 = __expf(s[mf][nf][3] - mnB);
                sumA += p0 + p1;
                sumB += p2 + p3;
                int colo = nf * 8 + 2 * c;
                *(float2*)&Ps[rb * PSD + colo] = make_float2(tf32r(p0), tf32r(p1));
                *(float2*)&Ps[(rb + 8) * PSD + colo] = make_float2(tf32r(p2), tf32r(p3));
            }
#pragma unroll
            for (int d = 1; d < 4; d <<= 1) {
                sumA += __shfl_xor_sync(0xffffffffu, sumA, d);
                sumB += __shfl_xor_sync(0xffffffffu, sumB, d);
            }
            l[mf][0] = l[mf][0] * aA + sumA;
            l[mf][1] = l[mf][1] * aB + sumB;
            m[mf][0] = mnA;
            m[mf][1] = mnB;
#pragma unroll
            for (int nf = 0; nf < 8; nf++) {
                o[mf][nf][0] *= aA; o[mf][nf][1] *= aA;
                o[mf][nf][2] *= aB; o[mf][nf][3] *= aB;
            }
        }
        __syncwarp();   // P rows are warp-private

        // O += P V  (V natural [key][h]; B-frags shared by 2 mf)
#pragma unroll
        for (int kk = 0; kk < 8; kk++) {
            uint32_t a[2][4];
#pragma unroll
            for (int mf = 0; mf < 2; mf++) {
                int rb = rowW + 16 * mf + r;
                a[mf][0] = Ps_u[rb * PSD + kk * 8 + c];
                a[mf][1] = Ps_u[(rb + 8) * PSD + kk * 8 + c];
                a[mf][2] = Ps_u[rb * PSD + kk * 8 + c + 4];
                a[mf][3] = Ps_u[(rb + 8) * PSD + kk * 8 + c + 4];
            }
#pragma unroll
            for (int nf = 0; nf < 8; nf++) {
                uint32_t b0 = Vs_u[(kk * 8 + c) * VSD + nf * 8 + r];
                uint32_t b1 = Vs_u[(kk * 8 + c + 4) * VSD + nf * 8 + r];
                mma_tf32(o[0][nf], a[0], b0, b1);
                mma_tf32(o[1][nf], a[1], b0, b1);
            }
        }
    }

    // write partial O (unnormalized) + per-row m, l
#pragma unroll
    for (int mf = 0; mf < 2; mf++) {
        int rb = rowW + 16 * mf + r;
#pragma unroll
        for (int nf = 0; nf < 8; nf++) {
            int colo = nf * 8 + 2 * c;
            *(float2*)&g_opart[(size_t)unit * 8192 + rb * 64 + colo] =
                make_float2(o[mf][nf][0], o[mf][nf][1]);
            *(float2*)&g_opart[(size_t)unit * 8192 + (rb + 8) * 64 + colo] =
                make_float2(o[mf][nf][2], o[mf][nf][3]);
        }
        if (c == 0) {
            g_mpart[unit * 128 + rb] = m[mf][0];
            g_mpart[unit * 128 + rb + 8] = m[mf][1];
            g_lpart[unit * 128 + rb] = l[mf][0];
            g_lpart[unit * 128 + rb + 8] = l[mf][1];
        }
    }
}

// ---------------------------------------------------------------------------
// Combine: LSE-merge up to 8 chunk partials per (b, 128-row qtile).
// 512 thr: row = tid>>2 (128 rows), quad = tid&3 (16 cols each).
// ---------------------------------------------------------------------------
__global__ __launch_bounds__(512) void attn_combine(float* __restrict__ out)
{
    const int qt = blockIdx.x, b = blockIdx.y;
    const int tid = threadIdx.x;
    const int row = tid >> 2;
    const int quad = tid & 3;
    const int nch = (2 * qt + 2 + CH - 1) / CH;
    const int ubase = (b * 32 + qt) * 8;

    float M = -1e30f;
    for (int i = 0; i < nch; i++)
        M = fmaxf(M, g_mpart[(ubase + i) * 128 + row]);

    float L = 0.f;
    float acc[16];
#pragma unroll
    for (int j = 0; j < 16; j++) acc[j] = 0.f;

    for (int i = 0; i < nch; i++) {
        float coef = __expf(g_mpart[(ubase + i) * 128 + row] - M);
        L += coef * g_lpart[(ubase + i) * 128 + row];
        const float* src =
            &g_opart[(size_t)(ubase + i) * 8192 + row * 64 + quad * 16];
#pragma unroll
        for (int j = 0; j < 4; j++) {
            float4 v = *(const float4*)&src[4 * j];
            acc[4 * j + 0] += coef * v.x;
            acc[4 * j + 1] += coef * v.y;
            acc[4 * j + 2] += coef * v.z;
            acc[4 * j + 3] += coef * v.w;
        }
    }

    float inv = 1.f / L;
    float* dst = &out[(size_t)b * TT * HH + (size_t)(qt * 128 + row) * HH + quad * 16];
#pragma unroll
    for (int j = 0; j < 4; j++) {
        float4 v = make_float4(acc[4 * j] * inv, acc[4 * j + 1] * inv,
                               acc[4 * j + 2] * inv, acc[4 * j + 3] * inv);
        *(float4*)&dst[4 * j] = v;
    }
}

// ---------------------------------------------------------------------------
extern "C" void kernel_launch(void* const* d_in, const int* in_sizes, int n_in,
                              void* d_out, int out_size)
{
    const float* x  = (const float*)d_in[0];
    const float* Wk = (const float*)d_in[1];
    const float* Wq = (const float*)d_in[2];
    const float* Wv = (const float*)d_in[3];
    float* out = (float*)d_out;

    cudaFuncSetAttribute(attn_partial, cudaFuncAttributeMaxDynamicSharedMemorySize, ATTN_SMEM);

    wt_kernel<<<384, 256>>>(Wk, Wq, Wv);
    proj_mma<<<256, 256>>>(x);
    attn_partial<<<dim3(8, 32, BB), 128, ATTN_SMEM>>>();
    attn_combine<<<dim3(32, BB), 512>>>(out);
}

// round 8
// speedup vs baseline: 8.8542x; 1.6543x over previous
#include <cuda_runtime.h>
#include <cuda_fp16.h>
#include <cstdint>

#define BB 4
#define TT 4096
#define CC 512
#define HH 64
#define SCALE 0.044194173824159216f   // 512^-0.5
#define CH 8                           // k-tiles (64 keys) per split-K chunk

// fp16 operands
__device__ __half g_qh[BB * TT * HH];      // pre-scaled q, [tok][h]
__device__ __half g_kh[BB * TT * HH];      // k, [tok][h]
__device__ __half g_vt[BB * HH * TT];      // v transposed, [b][h][t]
__device__ __half g_wh[192 * CC];          // W^T hi, [n][k]
__device__ __half g_wl[192 * CC];          // W^T lo
__device__ __half g_xh[BB * TT * CC];      // x hi, [tok][k]
__device__ __half g_xl[BB * TT * CC];      // x lo
// split-K partials (fp32): 4 b x 32 qtiles x 8 chunks
__device__ float g_opart[1024 * 128 * 64];
__device__ float g_mpart[1024 * 128];
__device__ float g_lpart[1024 * 128];

__device__ __forceinline__ uint32_t h2u(__half2 h) {
    union { __half2 h; uint32_t u; } cvt;
    cvt.h = h;
    return cvt.u;
}

__device__ __forceinline__ void mma_f16(float* d, const uint32_t* a,
                                        uint32_t b0, uint32_t b1) {
    asm volatile(
        "mma.sync.aligned.m16n8k16.row.col.f32.f16.f16.f32 "
        "{%0,%1,%2,%3}, {%4,%5,%6,%7}, {%8,%9}, {%0,%1,%2,%3};"
        : "+f"(d[0]), "+f"(d[1]), "+f"(d[2]), "+f"(d[3])
        : "r"(a[0]), "r"(a[1]), "r"(a[2]), "r"(a[3]), "r"(b0), "r"(b1));
}

__device__ __forceinline__ void cp16(uint32_t dst, const void* src) {
    asm volatile("cp.async.cg.shared.global [%0], [%1], 16;"
                 :: "r"(dst), "l"(src) : "memory");
}
#define CP_COMMIT() asm volatile("cp.async.commit_group;" ::: "memory")
#define CP_WAIT1() asm volatile("cp.async.wait_group 1;" ::: "memory")
#define CP_WAIT0() asm volatile("cp.async.wait_group 0;" ::: "memory")

// ---------------------------------------------------------------------------
// W transpose + fp16 hi/lo split
// ---------------------------------------------------------------------------
__global__ __launch_bounds__(256) void wsplit_kernel(
    const float* __restrict__ Wk,
    const float* __restrict__ Wq,
    const float* __restrict__ Wv)
{
    int idx = blockIdx.x * 256 + threadIdx.x;   // 384 x 256 = 98304 = 192*512
    int k = idx / 192, n = idx - k * 192;
    const float* W = (n < 64) ? Wk : (n < 128) ? Wq : Wv;
    float w = W[k * HH + (n & 63)];
    __half hi = __float2half_rn(w);
    g_wh[n * CC + k] = hi;
    g_wl[n * CC + k] = __float2half_rn(w - __half2float(hi));
}

// ---------------------------------------------------------------------------
// x -> fp16 hi/lo planes (4 floats per thread)
// ---------------------------------------------------------------------------
__global__ __launch_bounds__(256) void xsplit_kernel(const float* __restrict__ x)
{
    int t = blockIdx.x * 256 + threadIdx.x;     // 8192 x 256 = 2.1M
    float4 v = *(const float4*)&x[(size_t)t * 4];
    __half h0 = __float2half_rn(v.x), h1 = __float2half_rn(v.y);
    __half h2 = __float2half_rn(v.z), h3 = __float2half_rn(v.w);
    __half l0 = __float2half_rn(v.x - __half2float(h0));
    __half l1 = __float2half_rn(v.y - __half2float(h1));
    __half l2 = __float2half_rn(v.z - __half2float(h2));
    __half l3 = __float2half_rn(v.w - __half2float(h3));
    ((__half2*)g_xh)[t * 2]     = __halves2half2(h0, h1);
    ((__half2*)g_xh)[t * 2 + 1] = __halves2half2(h2, h3);
    ((__half2*)g_xl)[t * 2]     = __halves2half2(l0, l1);
    ((__half2*)g_xl)[t * 2 + 1] = __halves2half2(l2, l3);
}

// ---------------------------------------------------------------------------
// Projection: fp16 3-term (xh*wh + xh*wl + xl*wh), m16n8k16, fp32 accum.
// CTA 256 thr (8 warps): tile M=128 x N=192, K-chunk 32, cp.async dbl-buffer.
// Warp (mw = w>>2, nw = w&3): 64x48 warp tile (4 mf x 6 nf).
// smem halves/buffer: XH[128][40], XL, WH[192][40], WL = 25600 halves.
// ---------------------------------------------------------------------------
#define PXH 0
#define PXL 5120
#define PWH 10240
#define PWL 17920
#define PBUF 25600
#define PSMEM (2 * PBUF * 2)   // bytes = 102400

__global__ __launch_bounds__(256) void proj_mma()
{
    extern __shared__ __half smp[];
    uint32_t sbase;
    asm("{ .reg .u64 t; cvta.to.shared.u64 t, %1; cvt.u32.u64 %0, t; }"
        : "=r"(sbase) : "l"(smp));

    const int tid = threadIdx.x;
    const int w = tid >> 5;
    const int lane = tid & 31;
    const int r = lane >> 2;
    const int c = lane & 3;
    const int mw = w >> 2, nw = w & 3;
    const int row0 = blockIdx.x * 128;

    float acc[4][6][4];
#pragma unroll
    for (int mf = 0; mf < 4; mf++)
#pragma unroll
        for (int nf = 0; nf < 6; nf++)
#pragma unroll
            for (int j = 0; j < 4; j++) acc[mf][nf][j] = 0.f;

    auto issue = [&](int ck, int bufo) {
        const int k0 = ck * 32;
        for (int t = tid; t < 512; t += 256) {
            int rr = t >> 2, seg = t & 3;
            cp16(sbase + (bufo + PXH + rr * 40 + seg * 8) * 2,
                 &g_xh[(size_t)(row0 + rr) * CC + k0 + seg * 8]);
            cp16(sbase + (bufo + PXL + rr * 40 + seg * 8) * 2,
                 &g_xl[(size_t)(row0 + rr) * CC + k0 + seg * 8]);
        }
        for (int t = tid; t < 768; t += 256) {
            int n = t >> 2, seg = t & 3;
            cp16(sbase + (bufo + PWH + n * 40 + seg * 8) * 2,
                 &g_wh[n * CC + k0 + seg * 8]);
            cp16(sbase + (bufo + PWL + n * 40 + seg * 8) * 2,
                 &g_wl[n * CC + k0 + seg * 8]);
        }
    };

    issue(0, 0);
    CP_COMMIT();

    for (int ck = 0; ck < 16; ck++) {
        const int bufo = (ck & 1) * PBUF;
        if (ck + 1 < 16) {
            issue(ck + 1, ((ck + 1) & 1) * PBUF);
            CP_COMMIT();
            CP_WAIT1();
        } else {
            CP_WAIT0();
        }
        __syncthreads();

        const uint32_t* Xh32 = (const uint32_t*)(smp + bufo + PXH);
        const uint32_t* Xl32 = (const uint32_t*)(smp + bufo + PXL);
        const uint32_t* Wh32 = (const uint32_t*)(smp + bufo + PWH);
        const uint32_t* Wl32 = (const uint32_t*)(smp + bufo + PWL);

#pragma unroll
        for (int kk = 0; kk < 2; kk++) {
            uint32_t ah[4][4], al[4][4];
#pragma unroll
            for (int mf = 0; mf < 4; mf++) {
                int rb = 64 * mw + 16 * mf;
                int i0 = (rb + r) * 20 + kk * 8 + c;
                int i1 = (rb + 8 + r) * 20 + kk * 8 + c;
                ah[mf][0] = Xh32[i0]; ah[mf][1] = Xh32[i1];
                ah[mf][2] = Xh32[i0 + 4]; ah[mf][3] = Xh32[i1 + 4];
                al[mf][0] = Xl32[i0]; al[mf][1] = Xl32[i1];
                al[mf][2] = Xl32[i0 + 4]; al[mf][3] = Xl32[i1 + 4];
            }
#pragma unroll
            for (int nf = 0; nf < 6; nf++) {
                int bi = (48 * nw + 8 * nf + r) * 20 + kk * 8 + c;
                uint32_t bh0 = Wh32[bi], bh1 = Wh32[bi + 4];
                uint32_t bl0 = Wl32[bi], bl1 = Wl32[bi + 4];
#pragma unroll
                for (int mf = 0; mf < 4; mf++) {
                    mma_f16(acc[mf][nf], ah[mf], bh0, bh1);
                    mma_f16(acc[mf][nf], ah[mf], bl0, bl1);
                    mma_f16(acc[mf][nf], al[mf], bh0, bh1);
                }
            }
        }
        __syncthreads();
    }

    // epilogue: n<64 -> k, 64..127 -> q (scaled), 128..191 -> v (transposed)
#pragma unroll
    for (int mf = 0; mf < 4; mf++) {
#pragma unroll
        for (int nf = 0; nf < 6; nf++) {
            int n = 48 * nw + 8 * nf + 2 * c;
            int r0 = row0 + 64 * mw + 16 * mf + r;
            float v0 = acc[mf][nf][0], v1 = acc[mf][nf][1];
            float v2 = acc[mf][nf][2], v3 = acc[mf][nf][3];
            if (n < 64) {
                *(__half2*)&g_kh[(size_t)r0 * HH + n] = __floats2half2_rn(v0, v1);
                *(__half2*)&g_kh[(size_t)(r0 + 8) * HH + n] = __floats2half2_rn(v2, v3);
            } else if (n < 128) {
                *(__half2*)&g_qh[(size_t)r0 * HH + n - 64] =
                    __floats2half2_rn(v0 * SCALE, v1 * SCALE);
                *(__half2*)&g_qh[(size_t)(r0 + 8) * HH + n - 64] =
                    __floats2half2_rn(v2 * SCALE, v3 * SCALE);
            } else {
                int hh = n - 128;
                int b = r0 >> 12, t = r0 & 4095;
                size_t vb = (size_t)b * HH * TT;
                g_vt[vb + (size_t)hh * TT + t]       = __float2half_rn(v0);
                g_vt[vb + (size_t)(hh + 1) * TT + t] = __float2half_rn(v1);
                g_vt[vb + (size_t)hh * TT + t + 8]       = __float2half_rn(v2);
                g_vt[vb + (size_t)(hh + 1) * TT + t + 8] = __float2half_rn(v3);
            }
        }
    }
}

// ---------------------------------------------------------------------------
// Split-K flash attention partial, fp16 m16n8k16.
// CTA = 256 thr (8 warps), Q tile 128 rows; warp w owns rows 16w..16w+15.
// smem halves: Q[128][72], P[128][72], K[64][72], Vt[64][72] = 55.3 KB.
// ---------------------------------------------------------------------------
#define AQ 0
#define AP 9216
#define AK 18432
#define AV 23040
#define ATTN_SMEM ((23040 + 64 * 72) * 2)

__global__ __launch_bounds__(256) void attn_partial()
{
    const int ch = blockIdx.x, qt = blockIdx.y, b = blockIdx.z;
    const int nkt = 2 * qt + 2;
    if (ch * CH >= nkt) return;

    extern __shared__ __half sma[];
    uint32_t* Qs32 = (uint32_t*)(sma + AQ);
    uint32_t* Ps32 = (uint32_t*)(sma + AP);
    uint32_t* Ks32 = (uint32_t*)(sma + AK);
    uint32_t* Vs32 = (uint32_t*)(sma + AV);

    const int tid = threadIdx.x;
    const int w = tid >> 5;
    const int lane = tid & 31;
    const int r = lane >> 2;
    const int c = lane & 3;
    const int rowA = 16 * w + r;
    const int q0 = qt * 128;
    const size_t base = (size_t)b * TT * HH;
    const size_t vbase = (size_t)b * HH * TT;
    const int unit = (b * 32 + qt) * 8 + ch;

    // Q tile [128 x 64] halves -> smem (stride 72)
    for (int i = tid; i < 128 * 8; i += 256) {
        int row = i >> 3, seg = i & 7;
        *(uint4*)(sma + AQ + row * 72 + seg * 8) =
            *(const uint4*)&g_qh[base + (size_t)(q0 + row) * HH + seg * 8];
    }

    float mA = -1e30f, mB = -1e30f, lA = 0.f, lB = 0.f;
    float o[8][4];
#pragma unroll
    for (int nf = 0; nf < 8; nf++)
#pragma unroll
        for (int j = 0; j < 4; j++) o[nf][j] = 0.f;

    const int kt_end = min(ch * CH + CH, nkt);
    for (int kt = ch * CH; kt < kt_end; kt++) {
        const int k0 = kt * 64;
        __syncthreads();
        for (int i = tid; i < 64 * 8; i += 256) {
            int key = i >> 3, seg = i & 7;
            *(uint4*)(sma + AK + key * 72 + seg * 8) =
                *(const uint4*)&g_kh[base + (size_t)(k0 + key) * HH + seg * 8];
        }
        for (int i = tid; i < 64 * 8; i += 256) {
            int hh = i >> 3, seg = i & 7;
            *(uint4*)(sma + AV + hh * 72 + seg * 8) =
                *(const uint4*)&g_vt[vbase + (size_t)hh * TT + k0 + seg * 8];
        }
        __syncthreads();

        // S = Q K^T  (16 rows x 64 keys per warp, 4 k16-steps)
        float s[8][4];
#pragma unroll
        for (int nf = 0; nf < 8; nf++)
#pragma unroll
            for (int j = 0; j < 4; j++) s[nf][j] = 0.f;
#pragma unroll
        for (int kk = 0; kk < 4; kk++) {
            uint32_t a[4];
            int i0 = rowA * 36 + kk * 8 + c;
            int i1 = (rowA + 8) * 36 + kk * 8 + c;
            a[0] = Qs32[i0]; a[1] = Qs32[i1];
            a[2] = Qs32[i0 + 4]; a[3] = Qs32[i1 + 4];
#pragma unroll
            for (int nf = 0; nf < 8; nf++) {
                int bi = (nf * 8 + r) * 36 + kk * 8 + c;
                mma_f16(s[nf], a, Ks32[bi], Ks32[bi + 4]);
            }
        }

        // causal mask (only last two k-tiles of this q-tile's range)
        if (kt >= nkt - 2) {
            int gA = q0 + rowA;
#pragma unroll
            for (int nf = 0; nf < 8; nf++) {
                int col = k0 + nf * 8 + 2 * c;
                if (col > gA)     s[nf][0] = -1e30f;
                if (col + 1 > gA) s[nf][1] = -1e30f;
                if (col > gA + 8)     s[nf][2] = -1e30f;
                if (col + 1 > gA + 8) s[nf][3] = -1e30f;
            }
        }

        // online softmax (rows rowA / rowA+8); reduce over 4 c-lanes
        float xA = -1e30f, xB = -1e30f;
#pragma unroll
        for (int nf = 0; nf < 8; nf++) {
            xA = fmaxf(xA, fmaxf(s[nf][0], s[nf][1]));
            xB = fmaxf(xB, fmaxf(s[nf][2], s[nf][3]));
        }
#pragma unroll
        for (int d = 1; d < 4; d <<= 1) {
            xA = fmaxf(xA, __shfl_xor_sync(0xffffffffu, xA, d));
            xB = fmaxf(xB, __shfl_xor_sync(0xffffffffu, xB, d));
        }
        float mnA = fmaxf(mA, xA), mnB = fmaxf(mB, xB);
        float aA = __expf(mA - mnA), aB = __expf(mB - mnB);

        float sumA = 0.f, sumB = 0.f;
#pragma unroll
        for (int nf = 0; nf < 8; nf++) {
            float p0 = __expf(s[nf][0] - mnA);
            float p1 = __expf(s[nf][1] - mnA);
            float p2 = __expf(s[nf][2] - mnB);
            float p3 = __expf(s[nf][3] - mnB);
            sumA += p0 + p1;
            sumB += p2 + p3;
            Ps32[rowA * 36 + 4 * nf + c] = h2u(__floats2half2_rn(p0, p1));
            Ps32[(rowA + 8) * 36 + 4 * nf + c] = h2u(__floats2half2_rn(p2, p3));
        }
#pragma unroll
        for (int d = 1; d < 4; d <<= 1) {
            sumA += __shfl_xor_sync(0xffffffffu, sumA, d);
            sumB += __shfl_xor_sync(0xffffffffu, sumB, d);
        }
        lA = lA * aA + sumA;
        lB = lB * aB + sumB;
        mA = mnA;
        mB = mnB;
#pragma unroll
        for (int nf = 0; nf < 8; nf++) {
            o[nf][0] *= aA; o[nf][1] *= aA;
            o[nf][2] *= aB; o[nf][3] *= aB;
        }
        __syncwarp();   // P rows are warp-private

        // O += P V  (A from Ps, B from Vt[h][key], 4 k16-steps over keys)
#pragma unroll
        for (int kk = 0; kk < 4; kk++) {
            uint32_t a[4];
            int i0 = rowA * 36 + kk * 8 + c;
            int i1 = (rowA + 8) * 36 + kk * 8 + c;
            a[0] = Ps32[i0]; a[1] = Ps32[i1];
            a[2] = Ps32[i0 + 4]; a[3] = Ps32[i1 + 4];
#pragma unroll
            for (int nf = 0; nf < 8; nf++) {
                int bi = (nf * 8 + r) * 36 + kk * 8 + c;
                mma_f16(o[nf], a, Vs32[bi], Vs32[bi + 4]);
            }
        }
    }

    // write partial O (unnormalized) + per-row m, l
#pragma unroll
    for (int nf = 0; nf < 8; nf++) {
        int colo = nf * 8 + 2 * c;
        *(float2*)&g_opart[(size_t)unit * 8192 + rowA * 64 + colo] =
            make_float2(o[nf][0], o[nf][1]);
        *(float2*)&g_opart[(size_t)unit * 8192 + (rowA + 8) * 64 + colo] =
            make_float2(o[nf][2], o[nf][3]);
    }
    if (c == 0) {
        g_mpart[unit * 128 + rowA] = mA;
        g_mpart[unit * 128 + rowA + 8] = mB;
        g_lpart[unit * 128 + rowA] = lA;
        g_lpart[unit * 128 + rowA + 8] = lB;
    }
}

// ---------------------------------------------------------------------------
// Combine: LSE-merge up to 8 chunk partials per (b, 128-row qtile).
// ---------------------------------------------------------------------------
__global__ __launch_bounds__(512) void attn_combine(float* __restrict__ out)
{
    const int qt = blockIdx.x, b = blockIdx.y;
    const int tid = threadIdx.x;
    const int row = tid >> 2;
    const int quad = tid & 3;
    const int nch = (2 * qt + 2 + CH - 1) / CH;
    const int ubase = (b * 32 + qt) * 8;

    float M = -1e30f;
    for (int i = 0; i < nch; i++)
        M = fmaxf(M, g_mpart[(ubase + i) * 128 + row]);

    float L = 0.f;
    float acc[16];
#pragma unroll
    for (int j = 0; j < 16; j++) acc[j] = 0.f;

    for (int i = 0; i < nch; i++) {
        float coef = __expf(g_mpart[(ubase + i) * 128 + row] - M);
        L += coef * g_lpart[(ubase + i) * 128 + row];
        const float* src =
            &g_opart[(size_t)(ubase + i) * 8192 + row * 64 + quad * 16];
#pragma unroll
        for (int j = 0; j < 4; j++) {
            float4 v = *(const float4*)&src[4 * j];
            acc[4 * j + 0] += coef * v.x;
            acc[4 * j + 1] += coef * v.y;
            acc[4 * j + 2] += coef * v.z;
            acc[4 * j + 3] += coef * v.w;
        }
    }

    float inv = 1.f / L;
    float* dst = &out[(size_t)b * TT * HH + (size_t)(qt * 128 + row) * HH + quad * 16];
#pragma unroll
    for (int j = 0; j < 4; j++) {
        float4 v = make_float4(acc[4 * j] * inv, acc[4 * j + 1] * inv,
                               acc[4 * j + 2] * inv, acc[4 * j + 3] * inv);
        *(float4*)&dst[4 * j] = v;
    }
}

// ---------------------------------------------------------------------------
extern "C" void kernel_launch(void* const* d_in, const int* in_sizes, int n_in,
                              void* d_out, int out_size)
{
    const float* x  = (const float*)d_in[0];
    const float* Wk = (const float*)d_in[1];
    const float* Wq = (const float*)d_in[2];
    const float* Wv = (const float*)d_in[3];
    float* out = (float*)d_out;

    cudaFuncSetAttribute(proj_mma, cudaFuncAttributeMaxDynamicSharedMemorySize, PSMEM);
    cudaFuncSetAttribute(attn_partial, cudaFuncAttributeMaxDynamicSharedMemorySize, ATTN_SMEM);

    wsplit_kernel<<<384, 256>>>(Wk, Wq, Wv);
    xsplit_kernel<<<8192, 256>>>(x);
    proj_mma<<<128, 256, PSMEM>>>();
    attn_partial<<<dim3(8, 32, BB), 256, ATTN_SMEM>>>();
    attn_combine<<<dim3(32, BB), 512>>>(out);
}

// round 9
// speedup vs baseline: 10.5437x; 1.1908x over previous
#include <cuda_runtime.h>
#include <cuda_fp16.h>
#include <cstdint>

#define BB 4
#define TT 4096
#define CC 512
#define HH 64
#define SCALE 0.044194173824159216f   // 512^-0.5
#define CH 8                           // k-tiles (64 keys) per split-K chunk

// fp16 operands
__device__ __half g_qh[BB * TT * HH];      // pre-scaled q, [tok][h]
__device__ __half g_kh[BB * TT * HH];      // k, [tok][h]
__device__ __half g_vt[BB * HH * TT];      // v transposed, [b][h][t]
__device__ __half g_wh[192 * CC];          // W^T hi, [n][k]
__device__ __half g_wl[192 * CC];          // W^T lo
__device__ __half g_xh[BB * TT * CC];      // x hi, [tok][k]
__device__ __half g_xl[BB * TT * CC];      // x lo
// split-K partials (fp32)
__device__ float g_opart[1024 * 128 * 64];
__device__ float g_mpart[1024 * 128];
__device__ float g_lpart[1024 * 128];

__device__ __forceinline__ uint32_t h2u(__half2 h) {
    union { __half2 h; uint32_t u; } cvt;
    cvt.h = h;
    return cvt.u;
}

__device__ __forceinline__ void mma_f16(float* d, const uint32_t* a,
                                        uint32_t b0, uint32_t b1) {
    asm volatile(
        "mma.sync.aligned.m16n8k16.row.col.f32.f16.f16.f32 "
        "{%0,%1,%2,%3}, {%4,%5,%6,%7}, {%8,%9}, {%0,%1,%2,%3};"
        : "+f"(d[0]), "+f"(d[1]), "+f"(d[2]), "+f"(d[3])
        : "r"(a[0]), "r"(a[1]), "r"(a[2]), "r"(a[3]), "r"(b0), "r"(b1));
}

__device__ __forceinline__ void ldsm4(uint32_t& r0, uint32_t& r1,
                                      uint32_t& r2, uint32_t& r3, uint32_t addr) {
    asm volatile(
        "ldmatrix.sync.aligned.m8n8.x4.shared.b16 {%0,%1,%2,%3}, [%4];"
        : "=r"(r0), "=r"(r1), "=r"(r2), "=r"(r3) : "r"(addr));
}

__device__ __forceinline__ void cp16(uint32_t dst, const void* src) {
    asm volatile("cp.async.cg.shared.global [%0], [%1], 16;"
                 :: "r"(dst), "l"(src) : "memory");
}
#define CP_COMMIT() asm volatile("cp.async.commit_group;" ::: "memory")
#define CP_WAIT1() asm volatile("cp.async.wait_group 1;" ::: "memory")
#define CP_WAIT0() asm volatile("cp.async.wait_group 0;" ::: "memory")

// ---------------------------------------------------------------------------
// W transpose + fp16 hi/lo split
// ---------------------------------------------------------------------------
__global__ __launch_bounds__(256) void wsplit_kernel(
    const float* __restrict__ Wk,
    const float* __restrict__ Wq,
    const float* __restrict__ Wv)
{
    int idx = blockIdx.x * 256 + threadIdx.x;   // 384 x 256 = 98304 = 192*512
    int k = idx / 192, n = idx - k * 192;
    const float* W = (n < 64) ? Wk : (n < 128) ? Wq : Wv;
    float w = W[k * HH + (n & 63)];
    __half hi = __float2half_rn(w);
    g_wh[n * CC + k] = hi;
    g_wl[n * CC + k] = __float2half_rn(w - __half2float(hi));
}

// ---------------------------------------------------------------------------
// x -> fp16 hi/lo planes
// ---------------------------------------------------------------------------
__global__ __launch_bounds__(256) void xsplit_kernel(const float* __restrict__ x)
{
    int t = blockIdx.x * 256 + threadIdx.x;
    float4 v = *(const float4*)&x[(size_t)t * 4];
    __half h0 = __float2half_rn(v.x), h1 = __float2half_rn(v.y);
    __half h2 = __float2half_rn(v.z), h3 = __float2half_rn(v.w);
    __half l0 = __float2half_rn(v.x - __half2float(h0));
    __half l1 = __float2half_rn(v.y - __half2float(h1));
    __half l2 = __float2half_rn(v.z - __half2float(h2));
    __half l3 = __float2half_rn(v.w - __half2float(h3));
    ((__half2*)g_xh)[t * 2]     = __halves2half2(h0, h1);
    ((__half2*)g_xh)[t * 2 + 1] = __halves2half2(h2, h3);
    ((__half2*)g_xl)[t * 2]     = __halves2half2(l0, l1);
    ((__half2*)g_xl)[t * 2 + 1] = __halves2half2(l2, l3);
}

// ---------------------------------------------------------------------------
// Projection: fp16 3-term (xh*wh + xh*wl + xl*wh), m16n8k16, fp32 accum.
// (unchanged from R8)
// ---------------------------------------------------------------------------
#define PXH 0
#define PXL 5120
#define PWH 10240
#define PWL 17920
#define PBUF 25600
#define PSMEM (2 * PBUF * 2)

__global__ __launch_bounds__(256) void proj_mma()
{
    extern __shared__ __half smp[];
    uint32_t sbase;
    asm("{ .reg .u64 t; cvta.to.shared.u64 t, %1; cvt.u32.u64 %0, t; }"
        : "=r"(sbase) : "l"(smp));

    const int tid = threadIdx.x;
    const int w = tid >> 5;
    const int lane = tid & 31;
    const int r = lane >> 2;
    const int c = lane & 3;
    const int mw = w >> 2, nw = w & 3;
    const int row0 = blockIdx.x * 128;

    float acc[4][6][4];
#pragma unroll
    for (int mf = 0; mf < 4; mf++)
#pragma unroll
        for (int nf = 0; nf < 6; nf++)
#pragma unroll
            for (int j = 0; j < 4; j++) acc[mf][nf][j] = 0.f;

    auto issue = [&](int ck, int bufo) {
        const int k0 = ck * 32;
        for (int t = tid; t < 512; t += 256) {
            int rr = t >> 2, seg = t & 3;
            cp16(sbase + (bufo + PXH + rr * 40 + seg * 8) * 2,
                 &g_xh[(size_t)(row0 + rr) * CC + k0 + seg * 8]);
            cp16(sbase + (bufo + PXL + rr * 40 + seg * 8) * 2,
                 &g_xl[(size_t)(row0 + rr) * CC + k0 + seg * 8]);
        }
        for (int t = tid; t < 768; t += 256) {
            int n = t >> 2, seg = t & 3;
            cp16(sbase + (bufo + PWH + n * 40 + seg * 8) * 2,
                 &g_wh[n * CC + k0 + seg * 8]);
            cp16(sbase + (bufo + PWL + n * 40 + seg * 8) * 2,
                 &g_wl[n * CC + k0 + seg * 8]);
        }
    };

    issue(0, 0);
    CP_COMMIT();

    for (int ck = 0; ck < 16; ck++) {
        const int bufo = (ck & 1) * PBUF;
        if (ck + 1 < 16) {
            issue(ck + 1, ((ck + 1) & 1) * PBUF);
            CP_COMMIT();
            CP_WAIT1();
        } else {
            CP_WAIT0();
        }
        __syncthreads();

        const uint32_t* Xh32 = (const uint32_t*)(smp + bufo + PXH);
        const uint32_t* Xl32 = (const uint32_t*)(smp + bufo + PXL);
        const uint32_t* Wh32 = (const uint32_t*)(smp + bufo + PWH);
        const uint32_t* Wl32 = (const uint32_t*)(smp + bufo + PWL);

#pragma unroll
        for (int kk = 0; kk < 2; kk++) {
            uint32_t ah[4][4], al[4][4];
#pragma unroll
            for (int mf = 0; mf < 4; mf++) {
                int rb = 64 * mw + 16 * mf;
                int i0 = (rb + r) * 20 + kk * 8 + c;
                int i1 = (rb + 8 + r) * 20 + kk * 8 + c;
                ah[mf][0] = Xh32[i0]; ah[mf][1] = Xh32[i1];
                ah[mf][2] = Xh32[i0 + 4]; ah[mf][3] = Xh32[i1 + 4];
                al[mf][0] = Xl32[i0]; al[mf][1] = Xl32[i1];
                al[mf][2] = Xl32[i0 + 4]; al[mf][3] = Xl32[i1 + 4];
            }
#pragma unroll
            for (int nf = 0; nf < 6; nf++) {
                int bi = (48 * nw + 8 * nf + r) * 20 + kk * 8 + c;
                uint32_t bh0 = Wh32[bi], bh1 = Wh32[bi + 4];
                uint32_t bl0 = Wl32[bi], bl1 = Wl32[bi + 4];
#pragma unroll
                for (int mf = 0; mf < 4; mf++) {
                    mma_f16(acc[mf][nf], ah[mf], bh0, bh1);
                    mma_f16(acc[mf][nf], ah[mf], bl0, bl1);
                    mma_f16(acc[mf][nf], al[mf], bh0, bh1);
                }
            }
        }
        __syncthreads();
    }

#pragma unroll
    for (int mf = 0; mf < 4; mf++) {
#pragma unroll
        for (int nf = 0; nf < 6; nf++) {
            int n = 48 * nw + 8 * nf + 2 * c;
            int r0 = row0 + 64 * mw + 16 * mf + r;
            float v0 = acc[mf][nf][0], v1 = acc[mf][nf][1];
            float v2 = acc[mf][nf][2], v3 = acc[mf][nf][3];
            if (n < 64) {
                *(__half2*)&g_kh[(size_t)r0 * HH + n] = __floats2half2_rn(v0, v1);
                *(__half2*)&g_kh[(size_t)(r0 + 8) * HH + n] = __floats2half2_rn(v2, v3);
            } else if (n < 128) {
                *(__half2*)&g_qh[(size_t)r0 * HH + n - 64] =
                    __floats2half2_rn(v0 * SCALE, v1 * SCALE);
                *(__half2*)&g_qh[(size_t)(r0 + 8) * HH + n - 64] =
                    __floats2half2_rn(v2 * SCALE, v3 * SCALE);
            } else {
                int hh = n - 128;
                int b = r0 >> 12, t = r0 & 4095;
                size_t vb = (size_t)b * HH * TT;
                g_vt[vb + (size_t)hh * TT + t]       = __float2half_rn(v0);
                g_vt[vb + (size_t)(hh + 1) * TT + t] = __float2half_rn(v1);
                g_vt[vb + (size_t)hh * TT + t + 8]       = __float2half_rn(v2);
                g_vt[vb + (size_t)(hh + 1) * TT + t + 8] = __float2half_rn(v3);
            }
        }
    }
}

// ---------------------------------------------------------------------------
// Split-K flash attention partial, fp16 m16n8k16, ldmatrix + cp.async pipe.
// CTA = 256 thr (8 warps), Q tile 128 rows; warp w owns rows 16w..16w+15.
// smem bytes: Q[128][72h]=18432, K 2x[64][72h]=18432, V 2x=18432 -> 55296.
// P never touches smem (S-frag repacked as PV A-frag in registers).
// ---------------------------------------------------------------------------
#define QB 0
#define KB 18432
#define KBUF 9216
#define VB 36864
#define ATTN_SMEM 55296

__global__ __launch_bounds__(256) void attn_partial()
{
    const int ch = blockIdx.x, qt = blockIdx.y, b = blockIdx.z;
    const int nkt = 2 * qt + 2;
    if (ch * CH >= nkt) return;

    extern __shared__ __half sma[];
    uint32_t sbase;
    asm("{ .reg .u64 t; cvta.to.shared.u64 t, %1; cvt.u32.u64 %0, t; }"
        : "=r"(sbase) : "l"(sma));

    const int tid = threadIdx.x;
    const int w = tid >> 5;
    const int lane = tid & 31;
    const int r = lane >> 2;
    const int c = lane & 3;
    const int rowA = 16 * w + r;
    const int q0 = qt * 128;
    const size_t base = (size_t)b * TT * HH;
    const size_t vbase = (size_t)b * HH * TT;
    const int unit = (b * 32 + qt) * 8 + ch;

    // ldmatrix lane-base addresses (bytes)
    const uint32_t qa_lane = sbase + QB
        + (16 * w + (lane & 7) + ((lane >> 3) & 1) * 8) * 144
        + ((lane >> 4) & 1) * 16;
    const uint32_t b_lane =             // shared by K and V (same layout)
        ((lane & 7) + ((lane >> 4) & 1) * 8) * 144 + ((lane >> 3) & 1) * 16;

    // Q tile [128 x 64] halves -> smem (stride 72 halves)
    for (int i = tid; i < 128 * 8; i += 256) {
        int row = i >> 3, seg = i & 7;
        *(uint4*)((char*)sma + QB + row * 144 + seg * 16) =
            *(const uint4*)&g_qh[base + (size_t)(q0 + row) * HH + seg * 8];
    }

    const int kt_start = ch * CH;
    const int kt_end = min(kt_start + CH, nkt);

    // cp.async one K/V tile into buffer `buf`
    auto issue = [&](int kt, int buf) {
        const int k0 = kt * 64;
        for (int i = tid; i < 512; i += 256) {
            int row = i >> 3, seg = i & 7;
            cp16(sbase + KB + buf * KBUF + row * 144 + seg * 16,
                 &g_kh[base + (size_t)(k0 + row) * HH + seg * 8]);
            cp16(sbase + VB + buf * KBUF + row * 144 + seg * 16,
                 &g_vt[vbase + (size_t)row * TT + k0 + seg * 8]);
        }
    };

    issue(kt_start, kt_start & 1);
    CP_COMMIT();

    float mA = -1e30f, mB = -1e30f, lA = 0.f, lB = 0.f;
    float o[8][4];
#pragma unroll
    for (int nf = 0; nf < 8; nf++)
#pragma unroll
        for (int j = 0; j < 4; j++) o[nf][j] = 0.f;

    for (int kt = kt_start; kt < kt_end; kt++) {
        const uint32_t kbuf = sbase + KB + (uint32_t)(kt & 1) * KBUF;
        const uint32_t vbuf = sbase + VB + (uint32_t)(kt & 1) * KBUF;
        CP_WAIT0();
        __syncthreads();   // this tile ready; prior tile's readers done
        if (kt + 1 < kt_end) {
            issue(kt + 1, (kt + 1) & 1);
            CP_COMMIT();
        }

        // S = Q K^T  (16 rows x 64 keys per warp, 4 k16-steps, ldmatrix)
        float s[8][4];
#pragma unroll
        for (int nf = 0; nf < 8; nf++)
#pragma unroll
            for (int j = 0; j < 4; j++) s[nf][j] = 0.f;
#pragma unroll
        for (int kk = 0; kk < 4; kk++) {
            uint32_t a[4];
            ldsm4(a[0], a[1], a[2], a[3], qa_lane + kk * 32);
#pragma unroll
            for (int nfp = 0; nfp < 4; nfp++) {
                uint32_t b0, b1, b2, b3;
                ldsm4(b0, b1, b2, b3,
                      kbuf + b_lane + (uint32_t)(nfp * 2304 + kk * 32));
                mma_f16(s[2 * nfp], a, b0, b1);
                mma_f16(s[2 * nfp + 1], a, b2, b3);
            }
        }

        // causal mask (only last two k-tiles of this q-tile's range)
        if (kt >= nkt - 2) {
            int gA = q0 + rowA;
            int k0 = kt * 64;
#pragma unroll
            for (int nf = 0; nf < 8; nf++) {
                int col = k0 + nf * 8 + 2 * c;
                if (col > gA)     s[nf][0] = -1e30f;
                if (col + 1 > gA) s[nf][1] = -1e30f;
                if (col > gA + 8)     s[nf][2] = -1e30f;
                if (col + 1 > gA + 8) s[nf][3] = -1e30f;
            }
        }

        // online softmax (rows rowA / rowA+8); reduce over 4 c-lanes
        float xA = -1e30f, xB = -1e30f;
#pragma unroll
        for (int nf = 0; nf < 8; nf++) {
            xA = fmaxf(xA, fmaxf(s[nf][0], s[nf][1]));
            xB = fmaxf(xB, fmaxf(s[nf][2], s[nf][3]));
        }
#pragma unroll
        for (int d = 1; d < 4; d <<= 1) {
            xA = fmaxf(xA, __shfl_xor_sync(0xffffffffu, xA, d));
            xB = fmaxf(xB, __shfl_xor_sync(0xffffffffu, xB, d));
        }
        float mnA = fmaxf(mA, xA), mnB = fmaxf(mB, xB);
        float aA = __expf(mA - mnA), aB = __expf(mB - mnB);

        // exp + pack P fragments directly (no smem round trip)
        uint32_t pp[8][2];
        float sumA = 0.f, sumB = 0.f;
#pragma unroll
        for (int nf = 0; nf < 8; nf++) {
            float p0 = __expf(s[nf][0] - mnA);
            float p1 = __expf(s[nf][1] - mnA);
            float p2 = __expf(s[nf][2] - mnB);
            float p3 = __expf(s[nf][3] - mnB);
            sumA += p0 + p1;
            sumB += p2 + p3;
            pp[nf][0] = h2u(__floats2half2_rn(p0, p1));
            pp[nf][1] = h2u(__floats2half2_rn(p2, p3));
        }
#pragma unroll
        for (int d = 1; d < 4; d <<= 1) {
            sumA += __shfl_xor_sync(0xffffffffu, sumA, d);
            sumB += __shfl_xor_sync(0xffffffffu, sumB, d);
        }
        lA = lA * aA + sumA;
        lB = lB * aB + sumB;
        mA = mnA;
        mB = mnB;
#pragma unroll
        for (int nf = 0; nf < 8; nf++) {
            o[nf][0] *= aA; o[nf][1] *= aA;
            o[nf][2] *= aB; o[nf][3] *= aB;
        }

        // O += P V  (A = repacked S-frag; B from Vt via ldmatrix)
#pragma unroll
        for (int kk = 0; kk < 4; kk++) {
            uint32_t a[4] = { pp[2 * kk][0], pp[2 * kk][1],
                              pp[2 * kk + 1][0], pp[2 * kk + 1][1] };
#pragma unroll
            for (int nfp = 0; nfp < 4; nfp++) {
                uint32_t b0, b1, b2, b3;
                ldsm4(b0, b1, b2, b3,
                      vbuf + b_lane + (uint32_t)(nfp * 2304 + kk * 32));
                mma_f16(o[2 * nfp], a, b0, b1);
                mma_f16(o[2 * nfp + 1], a, b2, b3);
            }
        }
    }

    // write partial O (unnormalized) + per-row m, l
#pragma unroll
    for (int nf = 0; nf < 8; nf++) {
        int colo = nf * 8 + 2 * c;
        *(float2*)&g_opart[(size_t)unit * 8192 + rowA * 64 + colo] =
            make_float2(o[nf][0], o[nf][1]);
        *(float2*)&g_opart[(size_t)unit * 8192 + (rowA + 8) * 64 + colo] =
            make_float2(o[nf][2], o[nf][3]);
    }
    if (c == 0) {
        g_mpart[unit * 128 + rowA] = mA;
        g_mpart[unit * 128 + rowA + 8] = mB;
        g_lpart[unit * 128 + rowA] = lA;
        g_lpart[unit * 128 + rowA + 8] = lB;
    }
}

// ---------------------------------------------------------------------------
// Combine: LSE-merge up to 8 chunk partials. grid (32, BB, 4): z = row quarter.
// 256 thr: row = rq*32 + tid>>3, 8 cols per thread.
// ---------------------------------------------------------------------------
__global__ __launch_bounds__(256) void attn_combine(float* __restrict__ out)
{
    const int qt = blockIdx.x, b = blockIdx.y, rq = blockIdx.z;
    const int tid = threadIdx.x;
    const int row = rq * 32 + (tid >> 3);
    const int co = (tid & 7) * 8;
    const int nch = (2 * qt + 2 + CH - 1) / CH;
    const int ubase = (b * 32 + qt) * 8;

    float M = -1e30f;
    for (int i = 0; i < nch; i++)
        M = fmaxf(M, g_mpart[(ubase + i) * 128 + row]);

    float L = 0.f;
    float acc[8];
#pragma unroll
    for (int j = 0; j < 8; j++) acc[j] = 0.f;

    for (int i = 0; i < nch; i++) {
        float coef = __expf(g_mpart[(ubase + i) * 128 + row] - M);
        L += coef * g_lpart[(ubase + i) * 128 + row];
        const float* src = &g_opart[(size_t)(ubase + i) * 8192 + row * 64 + co];
#pragma unroll
        for (int j = 0; j < 2; j++) {
            float4 v = *(const float4*)&src[4 * j];
            acc[4 * j + 0] += coef * v.x;
            acc[4 * j + 1] += coef * v.y;
            acc[4 * j + 2] += coef * v.z;
            acc[4 * j + 3] += coef * v.w;
        }
    }

    float inv = 1.f / L;
    float* dst = &out[(size_t)b * TT * HH + (size_t)(qt * 128 + row) * HH + co];
#pragma unroll
    for (int j = 0; j < 2; j++) {
        float4 v = make_float4(acc[4 * j] * inv, acc[4 * j + 1] * inv,
                               acc[4 * j + 2] * inv, acc[4 * j + 3] * inv);
        *(float4*)&dst[4 * j] = v;
    }
}

// ---------------------------------------------------------------------------
extern "C" void kernel_launch(void* const* d_in, const int* in_sizes, int n_in,
                              void* d_out, int out_size)
{
    const float* x  = (const float*)d_in[0];
    const float* Wk = (const float*)d_in[1];
    const float* Wq = (const float*)d_in[2];
    const float* Wv = (const float*)d_in[3];
    float* out = (float*)d_out;

    cudaFuncSetAttribute(proj_mma, cudaFuncAttributeMaxDynamicSharedMemorySize, PSMEM);
    cudaFuncSetAttribute(attn_partial, cudaFuncAttributeMaxDynamicSharedMemorySize, ATTN_SMEM);

    wsplit_kernel<<<384, 256>>>(Wk, Wq, Wv);
    xsplit_kernel<<<8192, 256>>>(x);
    proj_mma<<<128, 256, PSMEM>>>();
    attn_partial<<<dim3(8, 32, BB), 256, ATTN_SMEM>>>();
    attn_combine<<<dim3(32, BB, 4), 256>>>(out);
}

// round 10
// speedup vs baseline: 11.5984x; 1.1000x over previous
#include <cuda_runtime.h>
#include <cuda_fp16.h>
#include <cstdint>

#define BB 4
#define TT 4096
#define CC 512
#define HH 64
#define LOG2E 1.4426950408889634f
#define SCALE 0.044194173824159216f   // 512^-0.5
#define CH 8                           // k-tiles (64 keys) per split-K chunk

// fp16 operands
__device__ __half g_qh[BB * TT * HH];      // q * SCALE * log2e, [tok][h]
__device__ __half g_kh[BB * TT * HH];      // k, [tok][h]
__device__ __half g_vt[BB * HH * TT];      // v transposed, [b][h][t]
__device__ __half g_wh[192 * CC];          // W^T hi, [n][k]
__device__ __half g_wl[192 * CC];          // W^T lo
// split-K partials (fp32); m is in log2 domain
__device__ float g_opart[1024 * 128 * 64];
__device__ float g_mpart[1024 * 128];
__device__ float g_lpart[1024 * 128];

__device__ __forceinline__ uint32_t h2u(__half2 h) {
    union { __half2 h; uint32_t u; } cvt;
    cvt.h = h;
    return cvt.u;
}

// fp32 pair -> fp16 hi + fp16 lo (packed)
__device__ __forceinline__ void split2(float2 v, uint32_t& hi, uint32_t& lo) {
    __half2 h = __floats2half2_rn(v.x, v.y);
    float2 hf = __half22float2(h);
    lo = h2u(__floats2half2_rn(v.x - hf.x, v.y - hf.y));
    hi = h2u(h);
}

__device__ __forceinline__ void mma_f16(float* d, const uint32_t* a,
                                        uint32_t b0, uint32_t b1) {
    asm volatile(
        "mma.sync.aligned.m16n8k16.row.col.f32.f16.f16.f32 "
        "{%0,%1,%2,%3}, {%4,%5,%6,%7}, {%8,%9}, {%0,%1,%2,%3};"
        : "+f"(d[0]), "+f"(d[1]), "+f"(d[2]), "+f"(d[3])
        : "r"(a[0]), "r"(a[1]), "r"(a[2]), "r"(a[3]), "r"(b0), "r"(b1));
}

__device__ __forceinline__ void ldsm4(uint32_t& r0, uint32_t& r1,
                                      uint32_t& r2, uint32_t& r3, uint32_t addr) {
    asm volatile(
        "ldmatrix.sync.aligned.m8n8.x4.shared.b16 {%0,%1,%2,%3}, [%4];"
        : "=r"(r0), "=r"(r1), "=r"(r2), "=r"(r3) : "r"(addr));
}

__device__ __forceinline__ void cp16(uint32_t dst, const void* src) {
    asm volatile("cp.async.cg.shared.global [%0], [%1], 16;"
                 :: "r"(dst), "l"(src) : "memory");
}
#define CP_COMMIT() asm volatile("cp.async.commit_group;" ::: "memory")
#define CP_WAIT1() asm volatile("cp.async.wait_group 1;" ::: "memory")
#define CP_WAIT0() asm volatile("cp.async.wait_group 0;" ::: "memory")

// ---------------------------------------------------------------------------
// W transpose + fp16 hi/lo split
// ---------------------------------------------------------------------------
__global__ __launch_bounds__(256) void wsplit_kernel(
    const float* __restrict__ Wk,
    const float* __restrict__ Wq,
    const float* __restrict__ Wv)
{
    int idx = blockIdx.x * 256 + threadIdx.x;   // 384 x 256 = 98304 = 192*512
    int k = idx / 192, n = idx - k * 192;
    const float* W = (n < 64) ? Wk : (n < 128) ? Wq : Wv;
    float w = W[k * HH + (n & 63)];
    __half hi = __float2half_rn(w);
    g_wh[n * CC + k] = hi;
    g_wl[n * CC + k] = __float2half_rn(w - __half2float(hi));
}

// ---------------------------------------------------------------------------
// Projection: fp16 3-term (xh*wh + xh*wl + xl*wh), m16n8k16, fp32 accum.
// x staged fp32 via cp.async, split to hi/lo fp16 in registers (no xsplit).
// CTA 256 thr (8 warps): tile M=128 x N=192, K-chunk 32, double-buffer.
// smem bytes/buffer: X fp32 [128][36] = 18432; W hi/lo [192][40h] = 15360 ea.
// ---------------------------------------------------------------------------
#define PXB(buf) ((buf) * 18432)
#define PWB(buf) (36864 + (buf) * 30720)
#define PWLO 15360
#define PSMEM 98304

__global__ __launch_bounds__(256) void proj_mma(const float* __restrict__ x)
{
    extern __shared__ char smp[];
    uint32_t sbase;
    asm("{ .reg .u64 t; cvta.to.shared.u64 t, %1; cvt.u32.u64 %0, t; }"
        : "=r"(sbase) : "l"(smp));

    const int tid = threadIdx.x;
    const int w = tid >> 5;
    const int lane = tid & 31;
    const int r = lane >> 2;
    const int c = lane & 3;
    const int mw = w >> 2, nw = w & 3;
    const int row0 = blockIdx.x * 128;

    float acc[4][6][4];
#pragma unroll
    for (int mf = 0; mf < 4; mf++)
#pragma unroll
        for (int nf = 0; nf < 6; nf++)
#pragma unroll
            for (int j = 0; j < 4; j++) acc[mf][nf][j] = 0.f;

    auto issue = [&](int ck, int buf) {
        const int k0 = ck * 32;
        for (int t = tid; t < 1024; t += 256) {       // X fp32: 128 rows x 8 segs
            int rr = t >> 3, seg = t & 7;
            cp16(sbase + PXB(buf) + rr * 144 + seg * 16,
                 &x[(size_t)(row0 + rr) * CC + k0 + seg * 4]);
        }
        for (int t = tid; t < 768; t += 256) {        // W hi+lo: 192 rows x 4 segs
            int n = t >> 2, seg = t & 3;
            cp16(sbase + PWB(buf) + n * 80 + seg * 16,
                 &g_wh[n * CC + k0 + seg * 8]);
            cp16(sbase + PWB(buf) + PWLO + n * 80 + seg * 16,
                 &g_wl[n * CC + k0 + seg * 8]);
        }
    };

    issue(0, 0);
    CP_COMMIT();

    for (int ck = 0; ck < 16; ck++) {
        const int buf = ck & 1;
        if (ck + 1 < 16) {
            issue(ck + 1, buf ^ 1);
            CP_COMMIT();
            CP_WAIT1();
        } else {
            CP_WAIT0();
        }
        __syncthreads();

        const float* Xf = (const float*)(smp + PXB(buf));
        const uint32_t* Wh32 = (const uint32_t*)(smp + PWB(buf));
        const uint32_t* Wl32 = (const uint32_t*)(smp + PWB(buf) + PWLO);

#pragma unroll
        for (int kk = 0; kk < 2; kk++) {
            uint32_t ah[4][4], al[4][4];
#pragma unroll
            for (int mf = 0; mf < 4; mf++) {
                int rb = 64 * mw + 16 * mf;
                const float* p0 = &Xf[(rb + r) * 36 + kk * 16 + 2 * c];
                const float* p1 = &Xf[(rb + 8 + r) * 36 + kk * 16 + 2 * c];
                split2(*(const float2*)p0,       ah[mf][0], al[mf][0]);
                split2(*(const float2*)p1,       ah[mf][1], al[mf][1]);
                split2(*(const float2*)(p0 + 8), ah[mf][2], al[mf][2]);
                split2(*(const float2*)(p1 + 8), ah[mf][3], al[mf][3]);
            }
#pragma unroll
            for (int nf = 0; nf < 6; nf++) {
                int bi = (48 * nw + 8 * nf + r) * 20 + kk * 8 + c;
                uint32_t bh0 = Wh32[bi], bh1 = Wh32[bi + 4];
                uint32_t bl0 = Wl32[bi], bl1 = Wl32[bi + 4];
#pragma unroll
                for (int mf = 0; mf < 4; mf++) {
                    mma_f16(acc[mf][nf], ah[mf], bh0, bh1);
                    mma_f16(acc[mf][nf], ah[mf], bl0, bl1);
                    mma_f16(acc[mf][nf], al[mf], bh0, bh1);
                }
            }
        }
        __syncthreads();
    }

    // epilogue: n<64 -> k, 64..127 -> q (scaled into log2 domain), 128..191 -> v^T
    const float qs = SCALE * LOG2E;
#pragma unroll
    for (int mf = 0; mf < 4; mf++) {
#pragma unroll
        for (int nf = 0; nf < 6; nf++) {
            int n = 48 * nw + 8 * nf + 2 * c;
            int r0 = row0 + 64 * mw + 16 * mf + r;
            float v0 = acc[mf][nf][0], v1 = acc[mf][nf][1];
            float v2 = acc[mf][nf][2], v3 = acc[mf][nf][3];
            if (n < 64) {
                *(__half2*)&g_kh[(size_t)r0 * HH + n] = __floats2half2_rn(v0, v1);
                *(__half2*)&g_kh[(size_t)(r0 + 8) * HH + n] = __floats2half2_rn(v2, v3);
            } else if (n < 128) {
                *(__half2*)&g_qh[(size_t)r0 * HH + n - 64] =
                    __floats2half2_rn(v0 * qs, v1 * qs);
                *(__half2*)&g_qh[(size_t)(r0 + 8) * HH + n - 64] =
                    __floats2half2_rn(v2 * qs, v3 * qs);
            } else {
                int hh = n - 128;
                int b = r0 >> 12, t = r0 & 4095;
                size_t vb = (size_t)b * HH * TT;
                g_vt[vb + (size_t)hh * TT + t]       = __float2half_rn(v0);
                g_vt[vb + (size_t)(hh + 1) * TT + t] = __float2half_rn(v1);
                g_vt[vb + (size_t)hh * TT + t + 8]       = __float2half_rn(v2);
                g_vt[vb + (size_t)(hh + 1) * TT + t + 8] = __float2half_rn(v3);
            }
        }
    }
}

// ---------------------------------------------------------------------------
// Split-K flash attention partial, fp16 m16n8k16, ldmatrix + cp.async pipe.
// Softmax in exp2 domain (q pre-scaled by SCALE*log2e).
// CTA = 256 thr (8 warps), Q tile 128 rows; warp w owns rows 16w..16w+15.
// ---------------------------------------------------------------------------
#define QB 0
#define KB 18432
#define KBUF 9216
#define VB 36864
#define ATTN_SMEM 55296

__global__ __launch_bounds__(256) void attn_partial()
{
    const int ch = blockIdx.x, qt = blockIdx.y, b = blockIdx.z;
    const int nkt = 2 * qt + 2;
    if (ch * CH >= nkt) return;

    extern __shared__ __half sma[];
    uint32_t sbase;
    asm("{ .reg .u64 t; cvta.to.shared.u64 t, %1; cvt.u32.u64 %0, t; }"
        : "=r"(sbase) : "l"(sma));

    const int tid = threadIdx.x;
    const int w = tid >> 5;
    const int lane = tid & 31;
    const int r = lane >> 2;
    const int c = lane & 3;
    const int rowA = 16 * w + r;
    const int q0 = qt * 128;
    const size_t base = (size_t)b * TT * HH;
    const size_t vbase = (size_t)b * HH * TT;
    const int unit = (b * 32 + qt) * 8 + ch;

    const uint32_t qa_lane = sbase + QB
        + (16 * w + (lane & 7) + ((lane >> 3) & 1) * 8) * 144
        + ((lane >> 4) & 1) * 16;
    const uint32_t b_lane =
        ((lane & 7) + ((lane >> 4) & 1) * 8) * 144 + ((lane >> 3) & 1) * 16;

    for (int i = tid; i < 128 * 8; i += 256) {
        int row = i >> 3, seg = i & 7;
        *(uint4*)((char*)sma + QB + row * 144 + seg * 16) =
            *(const uint4*)&g_qh[base + (size_t)(q0 + row) * HH + seg * 8];
    }

    const int kt_start = ch * CH;
    const int kt_end = min(kt_start + CH, nkt);

    auto issue = [&](int kt, int buf) {
        const int k0 = kt * 64;
        for (int i = tid; i < 512; i += 256) {
            int row = i >> 3, seg = i & 7;
            cp16(sbase + KB + buf * KBUF + row * 144 + seg * 16,
                 &g_kh[base + (size_t)(k0 + row) * HH + seg * 8]);
            cp16(sbase + VB + buf * KBUF + row * 144 + seg * 16,
                 &g_vt[vbase + (size_t)row * TT + k0 + seg * 8]);
        }
    };

    issue(kt_start, kt_start & 1);
    CP_COMMIT();

    float mA = -1e30f, mB = -1e30f, lA = 0.f, lB = 0.f;
    float o[8][4];
#pragma unroll
    for (int nf = 0; nf < 8; nf++)
#pragma unroll
        for (int j = 0; j < 4; j++) o[nf][j] = 0.f;

    for (int kt = kt_start; kt < kt_end; kt++) {
        const uint32_t kbuf = sbase + KB + (uint32_t)(kt & 1) * KBUF;
        const uint32_t vbuf = sbase + VB + (uint32_t)(kt & 1) * KBUF;
        CP_WAIT0();
        __syncthreads();
        if (kt + 1 < kt_end) {
            issue(kt + 1, (kt + 1) & 1);
            CP_COMMIT();
        }

        // S = Q K^T  (log2-domain logits)
        float s[8][4];
#pragma unroll
        for (int nf = 0; nf < 8; nf++)
#pragma unroll
            for (int j = 0; j < 4; j++) s[nf][j] = 0.f;
#pragma unroll
        for (int kk = 0; kk < 4; kk++) {
            uint32_t a[4];
            ldsm4(a[0], a[1], a[2], a[3], qa_lane + kk * 32);
#pragma unroll
            for (int nfp = 0; nfp < 4; nfp++) {
                uint32_t b0, b1, b2, b3;
                ldsm4(b0, b1, b2, b3,
                      kbuf + b_lane + (uint32_t)(nfp * 2304 + kk * 32));
                mma_f16(s[2 * nfp], a, b0, b1);
                mma_f16(s[2 * nfp + 1], a, b2, b3);
            }
        }

        if (kt >= nkt - 2) {
            int gA = q0 + rowA;
            int k0 = kt * 64;
#pragma unroll
            for (int nf = 0; nf < 8; nf++) {
                int col = k0 + nf * 8 + 2 * c;
                if (col > gA)     s[nf][0] = -1e30f;
                if (col + 1 > gA) s[nf][1] = -1e30f;
                if (col > gA + 8)     s[nf][2] = -1e30f;
                if (col + 1 > gA + 8) s[nf][3] = -1e30f;
            }
        }

        float xA = -1e30f, xB = -1e30f;
#pragma unroll
        for (int nf = 0; nf < 8; nf++) {
            xA = fmaxf(xA, fmaxf(s[nf][0], s[nf][1]));
            xB = fmaxf(xB, fmaxf(s[nf][2], s[nf][3]));
        }
#pragma unroll
        for (int d = 1; d < 4; d <<= 1) {
            xA = fmaxf(xA, __shfl_xor_sync(0xffffffffu, xA, d));
            xB = fmaxf(xB, __shfl_xor_sync(0xffffffffu, xB, d));
        }
        float mnA = fmaxf(mA, xA), mnB = fmaxf(mB, xB);
        float aA = exp2f(mA - mnA), aB = exp2f(mB - mnB);

        uint32_t pp[8][2];
        float sumA = 0.f, sumB = 0.f;
#pragma unroll
        for (int nf = 0; nf < 8; nf++) {
            float p0 = exp2f(s[nf][0] - mnA);
            float p1 = exp2f(s[nf][1] - mnA);
            float p2 = exp2f(s[nf][2] - mnB);
            float p3 = exp2f(s[nf][3] - mnB);
            sumA += p0 + p1;
            sumB += p2 + p3;
            pp[nf][0] = h2u(__floats2half2_rn(p0, p1));
            pp[nf][1] = h2u(__floats2half2_rn(p2, p3));
        }
#pragma unroll
        for (int d = 1; d < 4; d <<= 1) {
            sumA += __shfl_xor_sync(0xffffffffu, sumA, d);
            sumB += __shfl_xor_sync(0xffffffffu, sumB, d);
        }
        lA = lA * aA + sumA;
        lB = lB * aB + sumB;
        mA = mnA;
        mB = mnB;
#pragma unroll
        for (int nf = 0; nf < 8; nf++) {
            o[nf][0] *= aA; o[nf][1] *= aA;
            o[nf][2] *= aB; o[nf][3] *= aB;
        }

        // O += P V
#pragma unroll
        for (int kk = 0; kk < 4; kk++) {
            uint32_t a[4] = { pp[2 * kk][0], pp[2 * kk][1],
                              pp[2 * kk + 1][0], pp[2 * kk + 1][1] };
#pragma unroll
            for (int nfp = 0; nfp < 4; nfp++) {
                uint32_t b0, b1, b2, b3;
                ldsm4(b0, b1, b2, b3,
                      vbuf + b_lane + (uint32_t)(nfp * 2304 + kk * 32));
                mma_f16(o[2 * nfp], a, b0, b1);
                mma_f16(o[2 * nfp + 1], a, b2, b3);
            }
        }
    }

#pragma unroll
    for (int nf = 0; nf < 8; nf++) {
        int colo = nf * 8 + 2 * c;
        *(float2*)&g_opart[(size_t)unit * 8192 + rowA * 64 + colo] =
            make_float2(o[nf][0], o[nf][1]);
        *(float2*)&g_opart[(size_t)unit * 8192 + (rowA + 8) * 64 + colo] =
            make_float2(o[nf][2], o[nf][3]);
    }
    if (c == 0) {
        g_mpart[unit * 128 + rowA] = mA;
        g_mpart[unit * 128 + rowA + 8] = mB;
        g_lpart[unit * 128 + rowA] = lA;
        g_lpart[unit * 128 + rowA + 8] = lB;
    }
}

// ---------------------------------------------------------------------------
// Combine: LSE-merge (log2 domain) up to 8 chunk partials.
// grid (32, BB, 4): z = row quarter. 256 thr: 8 cols per thread.
// ---------------------------------------------------------------------------
__global__ __launch_bounds__(256) void attn_combine(float* __restrict__ out)
{
    const int qt = blockIdx.x, b = blockIdx.y, rq = blockIdx.z;
    const int tid = threadIdx.x;
    const int row = rq * 32 + (tid >> 3);
    const int co = (tid & 7) * 8;
    const int nch = (2 * qt + 2 + CH - 1) / CH;
    const int ubase = (b * 32 + qt) * 8;

    float M = -1e30f;
    for (int i = 0; i < nch; i++)
        M = fmaxf(M, g_mpart[(ubase + i) * 128 + row]);

    float L = 0.f;
    float acc[8];
#pragma unroll
    for (int j = 0; j < 8; j++) acc[j] = 0.f;

    for (int i = 0; i < nch; i++) {
        float coef = exp2f(g_mpart[(ubase + i) * 128 + row] - M);
        L += coef * g_lpart[(ubase + i) * 128 + row];
        const float* src = &g_opart[(size_t)(ubase + i) * 8192 + row * 64 + co];
#pragma unroll
        for (int j = 0; j < 2; j++) {
            float4 v = *(const float4*)&src[4 * j];
            acc[4 * j + 0] += coef * v.x;
            acc[4 * j + 1] += coef * v.y;
            acc[4 * j + 2] += coef * v.z;
            acc[4 * j + 3] += coef * v.w;
        }
    }

    float inv = 1.f / L;
    float* dst = &out[(size_t)b * TT * HH + (size_t)(qt * 128 + row) * HH + co];
#pragma unroll
    for (int j = 0; j < 2; j++) {
        float4 v = make_float4(acc[4 * j] * inv, acc[4 * j + 1] * inv,
                               acc[4 * j + 2] * inv, acc[4 * j + 3] * inv);
        *(float4*)&dst[4 * j] = v;
    }
}

// ---------------------------------------------------------------------------
extern "C" void kernel_launch(void* const* d_in, const int* in_sizes, int n_in,
                              void* d_out, int out_size)
{
    const float* x  = (const float*)d_in[0];
    const float* Wk = (const float*)d_in[1];
    const float* Wq = (const float*)d_in[2];
    const float* Wv = (const float*)d_in[3];
    float* out = (float*)d_out;

    cudaFuncSetAttribute(proj_mma, cudaFuncAttributeMaxDynamicSharedMemorySize, PSMEM);
    cudaFuncSetAttribute(attn_partial, cudaFuncAttributeMaxDynamicSharedMemorySize, ATTN_SMEM);

    wsplit_kernel<<<384, 256>>>(Wk, Wq, Wv);
    proj_mma<<<128, 256, PSMEM>>>(x);
    attn_partial<<<dim3(8, 32, BB), 256, ATTN_SMEM>>>();
    attn_combine<<<dim3(32, BB, 4), 256>>>(out);
}